// round 2
// baseline (speedup 1.0000x reference)
#include <cuda_runtime.h>
#include <cstdint>
#include <cstddef>

// Problem constants
#define Bq 8
#define Nq 4096
#define Pq 4096
#define Kq 32
#define Cq 128
#define Wq 16
#define EPSq 1e-5f

#define TPT 32                       // points per block
#define BLKS_PER_BATCH (Pq / TPT)    // 128
#define NBLK (Bq * BLKS_PER_BATCH)   // 1024

// Scratch (static device globals; allocation is forbidden)
__device__ float g_Ap[(4 * Cq + 16) * Cq];       // A'[d*C+c][j] + prefetch padding
__device__ float g_Y[(size_t)Bq * Pq * Cq];      // pre-LN activations per SOURCE batch
__device__ float g_ps[NBLK * 2 * Cq];            // per-(block,group) partial sums
__device__ float g_pq[NBLK * 2 * Cq];            // per-(block,group) partial sumsq
__device__ float g_scale[Cq];
__device__ float g_shift[Cq];
__device__ int   g_cnt[Bq];                      // multiplicity of each source batch

// ---- packed f32x2 helpers (Blackwell sm_103a) ----
__device__ __forceinline__ unsigned long long pk2(float x, float y) {
    unsigned long long r;
    asm("mov.b64 %0, {%1,%2};" : "=l"(r) : "f"(x), "f"(y));
    return r;
}
__device__ __forceinline__ void fma2(unsigned long long& d,
                                     unsigned long long a,
                                     unsigned long long b) {
    asm("fma.rn.f32x2 %0, %1, %2, %0;" : "+l"(d) : "l"(a), "l"(b));
}
__device__ __forceinline__ float2 up2(unsigned long long v) {
    float x, y;
    asm("mov.b64 {%0,%1}, %2;" : "=f"(x), "=f"(y) : "l"(v));
    return make_float2(x, y);
}

// ============================================================
// Kernel A: A'[d,c,j] = sum_w Ww[d,w]*Wl[c*16+w, j]  (d==3 uses bw)
//           + source-batch multiplicity counts
// ============================================================
__global__ void prep_kernel(const float* __restrict__ Ww,
                            const float* __restrict__ bw,
                            const float* __restrict__ Wl,
                            const int* __restrict__ didx) {
    int idx = blockIdx.x * blockDim.x + threadIdx.x;
    if (blockIdx.x == 0 && threadIdx.x < Bq) {
        int c = 0;
#pragma unroll
        for (int b = 0; b < Bq; b++) c += (didx[b] == (int)threadIdx.x);
        g_cnt[threadIdx.x] = c;
    }
    if (idx >= 4 * Cq * Cq) return;
    int d = idx >> 14;
    int c = (idx >> 7) & (Cq - 1);
    int j = idx & (Cq - 1);
    float acc = 0.f;
#pragma unroll
    for (int w = 0; w < Wq; w++) {
        float coef = (d < 3) ? Ww[d * Wq + w] : bw[w];
        acc = fmaf(coef, Wl[(c * Wq + w) * Cq + j], acc);
    }
    g_Ap[idx] = acc;
}

// ============================================================
// Kernel B: fused per-source-batch kernel.
//   S[d,c] = sum_k coef[k,d] * points[s, nbr[k], c]
//   y[j]   = sum_{d,c} S[d,c] * A'[d,c,j] + bl[j]
// 256 threads, TPT=32 points/block, dynamic smem.
// ============================================================
struct SmemLayout {
    float      s_S[TPT][4 * Cq];        // 64 KB
    ulonglong2 s_L[TPT][Kq];            // 16 KB  {pk2(L0,L1), pk2(L2,1)}
    uint32_t   s_off[TPT][Kq];          // 4 KB   byte offsets (nbr*512)
};
#define MAIN_SMEM ((int)sizeof(SmemLayout))

__global__ __launch_bounds__(256, 2) void main_kernel(
    const float* __restrict__ points,
    const float* __restrict__ lc,
    const int* __restrict__ nbr,
    const float* __restrict__ bl) {
    extern __shared__ char smem_raw[];
    SmemLayout* sm = reinterpret_cast<SmemLayout*>(smem_raw);

    const int tid = threadIdx.x;
    const int blk = blockIdx.x;
    const int s = blk >> 7;                      // source batch
    if (g_cnt[s] == 0) return;                   // unused source batch: skip
    const int p0 = (blk & (BLKS_PER_BATCH - 1)) * TPT;
    const float* pts = points + (size_t)s * Nq * Cq;
    const size_t base = ((size_t)s * Pq + p0) * Kq;

    // cooperative load: neighbor byte-offsets + packed local coords
    for (int i = tid; i < TPT * Kq; i += 256) {
        int t = i >> 5, k = i & 31;
        sm->s_off[t][k] = (uint32_t)nbr[base + (size_t)t * Kq + k] << 9;  // *512B
        const float* Lp = lc + (base + (size_t)t * Kq + k) * 3;
        float l0 = Lp[0], l1 = Lp[1], l2 = Lp[2];
        sm->s_L[t][k] = make_ulonglong2(pk2(l0, l1), pk2(l2, 1.0f));
    }
    __syncthreads();

    const int cj = tid & 127;    // channel (stage1) / out channel (stage2)
    const int grp = tid >> 7;    // 0/1: which half of the 32 points

    // ---- stage 1: S[d, cj] for this block's points ----
    {
        const char* ptsb = (const char*)(pts + cj);
        for (int t = grp * 16; t < grp * 16 + 16; t++) {
            unsigned long long a01 = 0ull, a23 = 0ull;
#pragma unroll 16
            for (int k = 0; k < Kq; k++) {
                float v = __ldg((const float*)(ptsb + sm->s_off[t][k]));
                unsigned long long v2 = pk2(v, v);
                ulonglong2 L = sm->s_L[t][k];
                fma2(a01, v2, L.x);
                fma2(a23, v2, L.y);
            }
            float2 f01 = up2(a01), f23 = up2(a23);
            sm->s_S[t][0 * Cq + cj] = f01.x;
            sm->s_S[t][1 * Cq + cj] = f01.y;
            sm->s_S[t][2 * Cq + cj] = f23.x;
            sm->s_S[t][3 * Cq + cj] = f23.y;
        }
    }
    __syncthreads();

    // ---- stage 2: y[j] = sum_i S[i] * A'[i][j], 16 points per thread ----
    unsigned long long acc[16];
#pragma unroll
    for (int t = 0; t < 16; t++) acc[t] = 0ull;
    const float* Ap = g_Ap + cj;
    const float* sS = &sm->s_S[grp * 16][0];

    // software-pipelined A' loads (depth 2 x 4 values); padding makes OOB safe
    float c0 = Ap[0 * Cq], c1 = Ap[1 * Cq], c2 = Ap[2 * Cq], c3 = Ap[3 * Cq];
    float d0 = Ap[4 * Cq], d1 = Ap[5 * Cq], d2 = Ap[6 * Cq], d3 = Ap[7 * Cq];

    for (int i = 0; i < 4 * Cq; i += 8) {
        const float* An = Ap + (i + 8) * Cq;
        float n0 = An[0 * Cq], n1 = An[1 * Cq], n2 = An[2 * Cq], n3 = An[3 * Cq];
        float n4 = An[4 * Cq], n5 = An[5 * Cq], n6 = An[6 * Cq], n7 = An[7 * Cq];

        unsigned long long a01 = pk2(c0, c1), a23 = pk2(c2, c3);
#pragma unroll
        for (int t = 0; t < 16; t++) {
            float4 sv = *reinterpret_cast<const float4*>(sS + t * 4 * Cq + i);
            fma2(acc[t], pk2(sv.x, sv.y), a01);
            fma2(acc[t], pk2(sv.z, sv.w), a23);
        }
        unsigned long long b01 = pk2(d0, d1), b23 = pk2(d2, d3);
#pragma unroll
        for (int t = 0; t < 16; t++) {
            float4 sv = *reinterpret_cast<const float4*>(sS + t * 4 * Cq + i + 4);
            fma2(acc[t], pk2(sv.x, sv.y), b01);
            fma2(acc[t], pk2(sv.z, sv.w), b23);
        }
        c0 = n0; c1 = n1; c2 = n2; c3 = n3;
        d0 = n4; d1 = n5; d2 = n6; d3 = n7;
    }

    const float blj = bl[cj];
    float lsum = 0.f, lsq = 0.f;
#pragma unroll
    for (int t = 0; t < 16; t++) {
        float2 f = up2(acc[t]);
        float y = f.x + f.y + blj;
        g_Y[((size_t)s * Pq + p0 + grp * 16 + t) * Cq + cj] = y;
        lsum += y;
        lsq += y * y;
    }
    g_ps[(size_t)blk * 256 + tid] = lsum;
    g_pq[(size_t)blk * 256 + tid] = lsq;
}

// ============================================================
// Kernel S: deterministic multiplicity-weighted reduction -> scale/shift
// ============================================================
__global__ void stats_kernel(const float* __restrict__ gamma,
                             const float* __restrict__ beta) {
    int j = threadIdx.x;  // 128 threads
    float s = 0.f, q = 0.f;
    for (int i = 0; i < NBLK; i++) {
        float w = (float)g_cnt[i >> 7];
        if (w == 0.f) continue;
        s += w * (g_ps[i * 256 + j] + g_ps[i * 256 + 128 + j]);
        q += w * (g_pq[i * 256 + j] + g_pq[i * 256 + 128 + j]);
    }
    const float inv = 1.0f / (float)(Bq * Pq);
    float mean = s * inv;
    float var = q * inv - mean * mean;
    float sc = rsqrtf(var + EPSq) * gamma[j];
    g_scale[j] = sc;
    g_shift[j] = beta[j] - mean * sc;
}

// ============================================================
// Kernel C: LN + relu + (b,p,j) -> (b,j,p) transpose (gathers via didx)
// ============================================================
__global__ __launch_bounds__(256) void out_kernel(float* __restrict__ out,
                                                  const int* __restrict__ didx) {
    __shared__ float tile[32][33];
    const int tx = threadIdx.x & 31;
    const int ty = threadIdx.x >> 5;  // 0..7
    const int b = blockIdx.z;
    const int src = didx[b];
    const int jt = blockIdx.y;   // 0..3
    const int pt = blockIdx.x;   // 0..127

    const int j = jt * 32 + tx;
    const float sc = g_scale[j];
    const float sh = g_shift[j];
#pragma unroll
    for (int r = 0; r < 4; r++) {
        int p = pt * 32 + ty + r * 8;
        float v = g_Y[((size_t)src * Pq + p) * Cq + j];
        tile[ty + r * 8][tx] = fmaxf(fmaf(v, sc, sh), 0.f);
    }
    __syncthreads();
#pragma unroll
    for (int r = 0; r < 4; r++) {
        int jj = jt * 32 + ty + r * 8;
        out[((size_t)b * Cq + jj) * Pq + pt * 32 + tx] = tile[tx][ty + r * 8];
    }
}

// ============================================================
// Launch
// ============================================================
extern "C" void kernel_launch(void* const* d_in, const int* in_sizes, int n_in,
                              void* d_out, int out_size) {
    const float* xyz    = (const float*)d_in[0];
    const float* points = (const float*)d_in[1];
    const float* lc     = (const float*)d_in[2];
    const int*   nbr    = (const int*)d_in[3];
    const int*   didx   = (const int*)d_in[4];
    const float* Ww     = (const float*)d_in[5];
    const float* bw     = (const float*)d_in[6];
    const float* Wl     = (const float*)d_in[7];
    const float* bl     = (const float*)d_in[8];
    const float* gamma  = (const float*)d_in[9];
    const float* beta   = (const float*)d_in[10];
    float* out = (float*)d_out;

    // xyz passthrough (first tuple element)
    cudaMemcpyAsync(out, xyz, (size_t)Bq * Pq * 3 * sizeof(float),
                    cudaMemcpyDeviceToDevice, 0);

    cudaFuncSetAttribute(main_kernel,
                         cudaFuncAttributeMaxDynamicSharedMemorySize, MAIN_SMEM);

    prep_kernel<<<256, 256>>>(Ww, bw, Wl, didx);
    main_kernel<<<NBLK, 256, MAIN_SMEM>>>(points, lc, nbr, bl);
    stats_kernel<<<1, Cq>>>(gamma, beta);

    dim3 g(Pq / 32, Cq / 32, Bq);
    out_kernel<<<g, 256>>>(out + (size_t)Bq * Pq * 3, didx);
}

// round 3
// speedup vs baseline: 1.7157x; 1.7157x over previous
#include <cuda_runtime.h>
#include <cstdint>
#include <cstddef>

// Problem constants
#define Bq 8
#define Nq 4096
#define Pq 4096
#define Kq 32
#define Cq 128
#define Wq 16
#define EPSq 1e-5f

#define TPT 16                       // points per block
#define BLKS_PER_BATCH (Pq / TPT)    // 256
#define NBLK (Bq * BLKS_PER_BATCH)   // 2048
#define NTILE 32                     // A' tiles (16 i-rows each)
#define NQUAD (4 * Cq * Cq / 4)      // 16384 float4 quads in A'

// Scratch (static device globals; allocation is forbidden)
__device__ float4 g_Ap4[NQUAD + 512];            // quad-interleaved A' + 1 tile pad
__device__ float  g_Y[(size_t)Bq * Pq * Cq];     // pre-LN activations per SOURCE batch
__device__ float  g_ps[NBLK * Cq];               // per-block partial sums
__device__ float  g_pq[NBLK * Cq];               // per-block partial sumsq
__device__ float  g_ps2[64 * Cq];
__device__ float  g_pq2[64 * Cq];
__device__ float  g_scale[Cq];
__device__ float  g_shift[Cq];
__device__ int    g_cnt[Bq];                     // multiplicity of each source batch

// ---- packed f32x2 helpers (Blackwell sm_103a) ----
__device__ __forceinline__ unsigned long long pk2(float x, float y) {
    unsigned long long r;
    asm("mov.b64 %0, {%1,%2};" : "=l"(r) : "f"(x), "f"(y));
    return r;
}
__device__ __forceinline__ void fma2(unsigned long long& d,
                                     unsigned long long a,
                                     unsigned long long b) {
    asm("fma.rn.f32x2 %0, %1, %2, %0;" : "+l"(d) : "l"(a), "l"(b));
}
__device__ __forceinline__ float2 up2(unsigned long long v) {
    float x, y;
    asm("mov.b64 {%0,%1}, %2;" : "=f"(x), "=f"(y) : "l"(v));
    return make_float2(x, y);
}

// ============================================================
// Kernel A: A'[i=d*128+c][j] = sum_w coef[d,w]*Wl[c*16+w, j]
//   (d<3: coef=Ww[d,w]; d==3: coef=bw[w])
//   emitted quad-interleaved: g_Ap4[(i>>2)*128 + j][i&3]
//   + source-batch multiplicity counts
// ============================================================
__global__ void prep_kernel(const float* __restrict__ Ww,
                            const float* __restrict__ bw,
                            const float* __restrict__ Wl,
                            const int* __restrict__ didx) {
    int idx = blockIdx.x * blockDim.x + threadIdx.x;
    if (blockIdx.x == 0 && threadIdx.x < Bq) {
        int c = 0;
#pragma unroll
        for (int b = 0; b < Bq; b++) c += (didx[b] == (int)threadIdx.x);
        g_cnt[threadIdx.x] = c;
    }
    if (idx >= 4 * Cq * Cq) return;
    int d = idx >> 14;
    int c = (idx >> 7) & (Cq - 1);
    int j = idx & (Cq - 1);
    float acc = 0.f;
#pragma unroll
    for (int w = 0; w < Wq; w++) {
        float coef = (d < 3) ? Ww[d * Wq + w] : bw[w];
        acc = fmaf(coef, Wl[(c * Wq + w) * Cq + j], acc);
    }
    int i = (d << 7) | c;
    ((float*)g_Ap4)[((size_t)(i >> 2) * Cq + j) * 4 + (i & 3)] = acc;
}

// ============================================================
// Kernel B: fused per-source-batch kernel.
//   stage 1: S[d,c] = sum_k coef[k,d] * points[s, nbr[k], c]
//   stage 2: y[j]   = sum_i S[i] * A'[i,j] + bl[j]   (A' tiled via smem)
// ============================================================
struct SmemLayout {
    float      s_S[TPT][4 * Cq];        // 32 KB
    ulonglong2 s_L[TPT][Kq];            // 8 KB   {pk2(L0,L1), pk2(L2,1)}
    uint32_t   s_off[TPT][Kq];          // 2 KB   byte offsets (nbr*512)
    float4     s_A[4][Cq];              // 8 KB   current A' tile (16 rows)
};
#define MAIN_SMEM ((int)sizeof(SmemLayout))

__global__ __launch_bounds__(128, 4) void main_kernel(
    const float* __restrict__ points,
    const float* __restrict__ lc,
    const int* __restrict__ nbr,
    const float* __restrict__ bl) {
    extern __shared__ char smem_raw[];
    SmemLayout* sm = reinterpret_cast<SmemLayout*>(smem_raw);

    const int tid = threadIdx.x;
    const int blk = blockIdx.x;
    const int s = blk >> 8;                      // source batch
    if (g_cnt[s] == 0) return;                   // unused source batch: skip
    const int p0 = (blk & (BLKS_PER_BATCH - 1)) * TPT;
    const float* pts = points + (size_t)s * Nq * Cq;
    const size_t base = ((size_t)s * Pq + p0) * Kq;

    // cooperative load: neighbor byte-offsets + packed local coords
    for (int i = tid; i < TPT * Kq; i += 128) {
        int t = i >> 5, k = i & 31;
        sm->s_off[t][k] = (uint32_t)nbr[base + (size_t)t * Kq + k] << 9;  // *512B
        const float* Lp = lc + (base + (size_t)t * Kq + k) * 3;
        float l0 = Lp[0], l1 = Lp[1], l2 = Lp[2];
        sm->s_L[t][k] = make_ulonglong2(pk2(l0, l1), pk2(l2, 1.0f));
    }
    __syncthreads();

    // ---- stage 1: thread owns channel c = tid ----
    {
        const char* ptsb = (const char*)(pts + tid);
        for (int t = 0; t < TPT; t++) {
            unsigned long long a01 = 0ull, a23 = 0ull;
#pragma unroll
            for (int k = 0; k < Kq; k++) {
                float v = __ldg((const float*)(ptsb + sm->s_off[t][k]));
                unsigned long long v2 = pk2(v, v);
                ulonglong2 L = sm->s_L[t][k];
                fma2(a01, v2, L.x);
                fma2(a23, v2, L.y);
            }
            float2 f01 = up2(a01), f23 = up2(a23);
            sm->s_S[t][0 * Cq + tid] = f01.x;
            sm->s_S[t][1 * Cq + tid] = f01.y;
            sm->s_S[t][2 * Cq + tid] = f23.x;
            sm->s_S[t][3 * Cq + tid] = f23.y;
        }
    }

    // ---- stage 2: A' streamed through smem tiles (16 rows each) ----
    unsigned long long acc[TPT];
#pragma unroll
    for (int t = 0; t < TPT; t++) acc[t] = 0ull;

    // prefetch tile 0 into registers
    const float4* Ab = g_Ap4 + tid;
    float4 pf0 = __ldg(Ab + 0 * Cq);
    float4 pf1 = __ldg(Ab + 1 * Cq);
    float4 pf2 = __ldg(Ab + 2 * Cq);
    float4 pf3 = __ldg(Ab + 3 * Cq);

    for (int kt = 0; kt < NTILE; kt++) {
        __syncthreads();    // previous tile fully consumed (kt=0: stage1 done)
        sm->s_A[0][tid] = pf0;
        sm->s_A[1][tid] = pf1;
        sm->s_A[2][tid] = pf2;
        sm->s_A[3][tid] = pf3;
        __syncthreads();

        // prefetch next tile (pad region at kt=31; values unused)
        const float4* An = Ab + (size_t)(kt + 1) * 4 * Cq;
        pf0 = __ldg(An + 0 * Cq);
        pf1 = __ldg(An + 1 * Cq);
        pf2 = __ldg(An + 2 * Cq);
        pf3 = __ldg(An + 3 * Cq);

#pragma unroll
        for (int iql = 0; iql < 4; iql++) {
            float4 av = sm->s_A[iql][tid];
            unsigned long long a01 = pk2(av.x, av.y);
            unsigned long long a23 = pk2(av.z, av.w);
            const int ib = kt * 16 + iql * 4;
#pragma unroll
            for (int t = 0; t < TPT; t++) {
                float4 sv = *reinterpret_cast<const float4*>(&sm->s_S[t][ib]);
                fma2(acc[t], pk2(sv.x, sv.y), a01);
                fma2(acc[t], pk2(sv.z, sv.w), a23);
            }
        }
    }

    const float blj = bl[tid];
    float lsum = 0.f, lsq = 0.f;
#pragma unroll
    for (int t = 0; t < TPT; t++) {
        float2 f = up2(acc[t]);
        float y = f.x + f.y + blj;
        g_Y[((size_t)s * Pq + p0 + t) * Cq + tid] = y;
        lsum += y;
        lsq += y * y;
    }
    g_ps[(size_t)blk * Cq + tid] = lsum;
    g_pq[(size_t)blk * Cq + tid] = lsq;
}

// ============================================================
// Stats: two-stage deterministic multiplicity-weighted reduction
// ============================================================
__global__ void stats1_kernel() {
    int j = threadIdx.x;                 // 128
    int r0 = blockIdx.x * (NBLK / 64);   // 32 rows per block
    float s = 0.f, q = 0.f;
    for (int r = 0; r < NBLK / 64; r++) {
        int row = r0 + r;
        float w = (float)g_cnt[row >> 8];
        s += w * g_ps[(size_t)row * Cq + j];
        q += w * g_pq[(size_t)row * Cq + j];
    }
    g_ps2[blockIdx.x * Cq + j] = s;
    g_pq2[blockIdx.x * Cq + j] = q;
}

__global__ void stats2_kernel(const float* __restrict__ gamma,
                              const float* __restrict__ beta) {
    int j = threadIdx.x;  // 128
    float s = 0.f, q = 0.f;
    for (int r = 0; r < 64; r++) {
        s += g_ps2[r * Cq + j];
        q += g_pq2[r * Cq + j];
    }
    const float inv = 1.0f / (float)(Bq * Pq);
    float mean = s * inv;
    float var = q * inv - mean * mean;
    float sc = rsqrtf(var + EPSq) * gamma[j];
    g_scale[j] = sc;
    g_shift[j] = beta[j] - mean * sc;
}

// ============================================================
// Kernel C: LN + relu + (b,p,j) -> (b,j,p) transpose (gathers via didx)
// ============================================================
__global__ __launch_bounds__(256) void out_kernel(float* __restrict__ out,
                                                  const int* __restrict__ didx) {
    __shared__ float tile[32][33];
    const int tx = threadIdx.x & 31;
    const int ty = threadIdx.x >> 5;  // 0..7
    const int b = blockIdx.z;
    const int src = didx[b];
    const int jt = blockIdx.y;   // 0..3
    const int pt = blockIdx.x;   // 0..127

    const int j = jt * 32 + tx;
    const float sc = g_scale[j];
    const float sh = g_shift[j];
#pragma unroll
    for (int r = 0; r < 4; r++) {
        int p = pt * 32 + ty + r * 8;
        float v = g_Y[((size_t)src * Pq + p) * Cq + j];
        tile[ty + r * 8][tx] = fmaxf(fmaf(v, sc, sh), 0.f);
    }
    __syncthreads();
#pragma unroll
    for (int r = 0; r < 4; r++) {
        int jj = jt * 32 + ty + r * 8;
        out[((size_t)b * Cq + jj) * Pq + pt * 32 + tx] = tile[tx][ty + r * 8];
    }
}

// ============================================================
// Launch
// ============================================================
extern "C" void kernel_launch(void* const* d_in, const int* in_sizes, int n_in,
                              void* d_out, int out_size) {
    const float* xyz    = (const float*)d_in[0];
    const float* points = (const float*)d_in[1];
    const float* lc     = (const float*)d_in[2];
    const int*   nbr    = (const int*)d_in[3];
    const int*   didx   = (const int*)d_in[4];
    const float* Ww     = (const float*)d_in[5];
    const float* bw     = (const float*)d_in[6];
    const float* Wl     = (const float*)d_in[7];
    const float* bl     = (const float*)d_in[8];
    const float* gamma  = (const float*)d_in[9];
    const float* beta   = (const float*)d_in[10];
    float* out = (float*)d_out;

    // xyz passthrough (first tuple element)
    cudaMemcpyAsync(out, xyz, (size_t)Bq * Pq * 3 * sizeof(float),
                    cudaMemcpyDeviceToDevice, 0);

    cudaFuncSetAttribute(main_kernel,
                         cudaFuncAttributeMaxDynamicSharedMemorySize, MAIN_SMEM);

    prep_kernel<<<256, 256>>>(Ww, bw, Wl, didx);
    main_kernel<<<NBLK, 128, MAIN_SMEM>>>(points, lc, nbr, bl);
    stats1_kernel<<<64, Cq>>>();
    stats2_kernel<<<1, Cq>>>(gamma, beta);

    dim3 g(Pq / 32, Cq / 32, Bq);
    out_kernel<<<g, 256>>>(out + (size_t)Bq * Pq * 3, didx);
}

// round 5
// speedup vs baseline: 3.0170x; 1.7585x over previous
#include <cuda_runtime.h>
#include <cuda_bf16.h>
#include <cstdint>
#include <cstddef>

// Problem constants
#define Bq 8
#define Nq 4096
#define Pq 4096
#define Kq 32
#define Cq 128
#define Wq 16
#define EPSq 1e-5f

#define TPT 16                        // points per gather block
#define GBLK_PER_B (Pq / TPT)         // 256
#define NPTILE (Pq / 128)             // 32 p-tiles per batch
#define NBLK2 (Bq * NPTILE)           // 256 GEMM blocks

// ------------------- device globals (no allocation allowed) -------------------
__device__ __align__(256) __nv_bfloat16 g_Shi[(size_t)Bq * Pq * 512];  // [s][p][i]
__device__ __align__(256) __nv_bfloat16 g_Slo[(size_t)Bq * Pq * 512];
__device__ __align__(256) __nv_bfloat16 g_Ahi[128 * 512];              // [j][i]
__device__ __align__(256) __nv_bfloat16 g_Alo[128 * 512];
__device__ float g_Yt[(size_t)Bq * Cq * Pq];                           // [s][j][p]
__device__ float g_ps[NBLK2 * Cq];
__device__ float g_pq[NBLK2 * Cq];
__device__ float g_ps2[32 * Cq];
__device__ float g_pq2[32 * Cq];
__device__ float g_scale[Cq];
__device__ float g_shift[Cq];
__device__ int   g_cnt[Bq];

// ------------------- helpers -------------------
__device__ __forceinline__ unsigned long long pk2(float x, float y) {
    unsigned long long r;
    asm("mov.b64 %0, {%1,%2};" : "=l"(r) : "f"(x), "f"(y));
    return r;
}
__device__ __forceinline__ void fma2(unsigned long long& d,
                                     unsigned long long a,
                                     unsigned long long b) {
    asm("fma.rn.f32x2 %0, %1, %2, %0;" : "+l"(d) : "l"(a), "l"(b));
}
__device__ __forceinline__ float2 up2(unsigned long long v) {
    float x, y;
    asm("mov.b64 {%0,%1}, %2;" : "=f"(x), "=f"(y) : "l"(v));
    return make_float2(x, y);
}
__device__ __forceinline__ uint32_t smem_to_u32(const void* p) {
    uint32_t a;
    asm("{ .reg .u64 t; cvta.to.shared.u64 t, %1; cvt.u32.u64 %0, t; }"
        : "=r"(a) : "l"(p));
    return a;
}

#define CP_ASYNC16(dst, src) \
    asm volatile("cp.async.cg.shared.global [%0], [%1], 16;" \
                 :: "r"(dst), "l"(src) : "memory")
#define CP_COMMIT() asm volatile("cp.async.commit_group;" ::: "memory")
#define CP_WAIT(n)  asm volatile("cp.async.wait_group %0;" :: "n"(n) : "memory")

__device__ __forceinline__ void ldsm_x4(uint32_t addr, uint32_t* r) {
    asm volatile("ldmatrix.sync.aligned.m8n8.x4.shared.b16 {%0,%1,%2,%3}, [%4];"
                 : "=r"(r[0]), "=r"(r[1]), "=r"(r[2]), "=r"(r[3]) : "r"(addr));
}
__device__ __forceinline__ void mma_bf16(float* c, const uint32_t* a,
                                         uint32_t b0, uint32_t b1) {
    asm volatile(
        "mma.sync.aligned.m16n8k16.row.col.f32.bf16.bf16.f32 "
        "{%0,%1,%2,%3}, {%4,%5,%6,%7}, {%8,%9}, {%0,%1,%2,%3};"
        : "+f"(c[0]), "+f"(c[1]), "+f"(c[2]), "+f"(c[3])
        : "r"(a[0]), "r"(a[1]), "r"(a[2]), "r"(a[3]), "r"(b0), "r"(b1));
}

// ============================================================
// prep: A'[i=d*128+c][j] -> bf16 hi/lo, transposed to [j][i]; batch counts
// ============================================================
__global__ void prep_kernel(const float* __restrict__ Ww,
                            const float* __restrict__ bw,
                            const float* __restrict__ Wl,
                            const int* __restrict__ didx) {
    int idx = blockIdx.x * blockDim.x + threadIdx.x;
    if (blockIdx.x == 0 && threadIdx.x < Bq) {
        int c = 0;
#pragma unroll
        for (int b = 0; b < Bq; b++) c += (didx[b] == (int)threadIdx.x);
        g_cnt[threadIdx.x] = c;
    }
    if (idx >= 4 * Cq * Cq) return;
    int d = idx >> 14;
    int c = (idx >> 7) & (Cq - 1);
    int j = idx & (Cq - 1);
    float acc = 0.f;
#pragma unroll
    for (int w = 0; w < Wq; w++) {
        float coef = (d < 3) ? Ww[d * Wq + w] : bw[w];
        acc = fmaf(coef, Wl[(c * Wq + w) * Cq + j], acc);
    }
    int i = (d << 7) | c;
    __nv_bfloat16 h = __float2bfloat16_rn(acc);
    __nv_bfloat16 l = __float2bfloat16_rn(acc - __bfloat162float(h));
    g_Ahi[(size_t)j * 512 + i] = h;
    g_Alo[(size_t)j * 512 + i] = l;
}

// ============================================================
// gather: S[p,i] = sum_k coef[k,d] * points[s, nbr[k], c]; emit bf16 hi/lo
// ============================================================
__global__ __launch_bounds__(128, 8) void gather_kernel(
    const float* __restrict__ points,
    const float* __restrict__ lc,
    const int* __restrict__ nbr) {
    __shared__ ulonglong2 s_L[TPT][Kq];
    __shared__ uint32_t s_off[TPT][Kq];

    const int tid = threadIdx.x;
    const int s = blockIdx.y;
    if (g_cnt[s] == 0) return;
    const int p0 = blockIdx.x * TPT;
    const float* pts = points + (size_t)s * Nq * Cq;
    const size_t base = ((size_t)s * Pq + p0) * Kq;

    for (int i = tid; i < TPT * Kq; i += 128) {
        int t = i >> 5, k = i & 31;
        s_off[t][k] = (uint32_t)nbr[base + (size_t)t * Kq + k] << 9;
        const float* Lp = lc + (base + (size_t)t * Kq + k) * 3;
        s_L[t][k] = make_ulonglong2(pk2(Lp[0], Lp[1]), pk2(Lp[2], 1.0f));
    }
    __syncthreads();

    const char* ptsb = (const char*)(pts + tid);
    for (int t = 0; t < TPT; t++) {
        unsigned long long a01 = 0ull, a23 = 0ull;
#pragma unroll
        for (int k = 0; k < Kq; k++) {
            float v = __ldg((const float*)(ptsb + s_off[t][k]));
            unsigned long long v2 = pk2(v, v);
            ulonglong2 L = s_L[t][k];
            fma2(a01, v2, L.x);
            fma2(a23, v2, L.y);
        }
        float2 f01 = up2(a01), f23 = up2(a23);
        const size_t rb = ((size_t)s * Pq + p0 + t) * 512;
        float vals[4] = {f01.x, f01.y, f23.x, f23.y};
#pragma unroll
        for (int d = 0; d < 4; d++) {
            __nv_bfloat16 h = __float2bfloat16_rn(vals[d]);
            __nv_bfloat16 l = __float2bfloat16_rn(vals[d] - __bfloat162float(h));
            g_Shi[rb + d * 128 + tid] = h;
            g_Slo[rb + d * 128 + tid] = l;
        }
    }
}

// ============================================================
// GEMM: Y[p,j] = S[p,i] * A'[j,i]^T  via mma.sync bf16 hi/lo split
//   block: 256 thr (8 warps, 4x2), tile M=128(p) N=128(j), K chunks of 32
//   smem rows: 32 bf16 = 64B data padded to 80B (conflict-free ldmatrix)
// ============================================================
#define TILE_B 10240                 // 128 rows * 80B
#define OFF_SHI 0
#define OFF_SLO (TILE_B)
#define OFF_AHI (2 * TILE_B)
#define OFF_ALO (3 * TILE_B)
#define BUF_B (4 * TILE_B)           // 40960
#define GSM_TOTAL (2 * BUF_B)        // 81920

__global__ __launch_bounds__(256, 2) void gemm_kernel(const float* __restrict__ bl) {
    extern __shared__ __align__(128) char sm[];
    const int tid = threadIdx.x;
    const int wid = tid >> 5;
    const int L = tid & 31;
    const int srcb = blockIdx.y;
    if (g_cnt[srcb] == 0) return;
    const int pt = blockIdx.x;
    const int wm = wid >> 1;     // 0..3  (p dim)
    const int wn = wid & 1;      // 0..1  (j dim)

    const uint32_t smb = smem_to_u32(sm);
    const __nv_bfloat16* Shi = g_Shi + ((size_t)srcb * Pq + pt * 128) * 512;
    const __nv_bfloat16* Slo = g_Slo + ((size_t)srcb * Pq + pt * 128) * 512;

    // per-thread copy units: u = tid + {0,256}; r = u>>2 (row), seg = u&3
    const int r0c = tid >> 2, seg0 = tid & 3;

    float acc[2][8][4];
#pragma unroll
    for (int mt = 0; mt < 2; mt++)
#pragma unroll
        for (int nt = 0; nt < 8; nt++)
#pragma unroll
            for (int q = 0; q < 4; q++) acc[mt][nt][q] = 0.f;

    // fragment smem addresses (lane-dependent parts precomputed)
    const int grp = L >> 3, lr = L & 7;
    // A (S): row = wm*32 + mt*16 + (grp&1)*8 + lr ; seg = 2*ks + (grp>>1)
    const uint32_t aRow = (uint32_t)(wm * 32 + (grp & 1) * 8 + lr) * 80
                        + (uint32_t)(grp >> 1) * 16;
    // B (A'): row = wn*64 + ng*16 + (grp>>1)*8 + lr ; seg = 2*ks + (grp&1)
    const uint32_t bRow = (uint32_t)(wn * 64 + (grp >> 1) * 8 + lr) * 80
                        + (uint32_t)(grp & 1) * 16;

#define ISSUE(kc, buf) do {                                                     \
        uint32_t bb = smb + (buf) * BUF_B;                                      \
        _Pragma("unroll")                                                       \
        for (int ii = 0; ii < 2; ii++) {                                        \
            int rr = r0c + ii * 64;                                             \
            uint32_t dsto = (uint32_t)rr * 80 + (uint32_t)seg0 * 16;            \
            size_t go = (size_t)rr * 512 + (size_t)(kc) * 32 + seg0 * 8;        \
            CP_ASYNC16(bb + OFF_SHI + dsto, (const char*)(Shi + go));           \
            CP_ASYNC16(bb + OFF_SLO + dsto, (const char*)(Slo + go));           \
            CP_ASYNC16(bb + OFF_AHI + dsto, (const char*)(g_Ahi + go));         \
            CP_ASYNC16(bb + OFF_ALO + dsto, (const char*)(g_Alo + go));         \
        }                                                                       \
        CP_COMMIT();                                                            \
    } while (0)

    ISSUE(0, 0);

#pragma unroll 1
    for (int kc = 0; kc < 16; kc++) {
        if (kc < 15) { ISSUE(kc + 1, (kc + 1) & 1); CP_WAIT(1); }
        else         { CP_WAIT(0); }
        __syncthreads();

        const uint32_t bb = smb + (kc & 1) * BUF_B;
#pragma unroll
        for (int ks = 0; ks < 2; ks++) {
            uint32_t ah[2][4], al[2][4];
#pragma unroll
            for (int mt = 0; mt < 2; mt++) {
                uint32_t ao = aRow + (uint32_t)mt * (16 * 80) + (uint32_t)ks * 32;
                ldsm_x4(bb + OFF_SHI + ao, ah[mt]);
                ldsm_x4(bb + OFF_SLO + ao, al[mt]);
            }
#pragma unroll
            for (int ng = 0; ng < 4; ng++) {
                uint32_t bh[4], blo[4];
                uint32_t bo = bRow + (uint32_t)ng * (16 * 80) + (uint32_t)ks * 32;
                ldsm_x4(bb + OFF_AHI + bo, bh);
                ldsm_x4(bb + OFF_ALO + bo, blo);
#pragma unroll
                for (int mt = 0; mt < 2; mt++) {
#pragma unroll
                    for (int t2 = 0; t2 < 2; t2++) {
                        float* c = acc[mt][2 * ng + t2];
                        mma_bf16(c, ah[mt], bh[2 * t2], bh[2 * t2 + 1]);
                        mma_bf16(c, ah[mt], blo[2 * t2], blo[2 * t2 + 1]);
                        mma_bf16(c, al[mt], bh[2 * t2], bh[2 * t2 + 1]);
                    }
                }
            }
        }
        __syncthreads();
    }

    // ---- epilogue: C frags -> smem [j][132] -> coalesced Y + LN partials ----
    float* yt = (float*)sm;
    {
        const int pb = wm * 32 + (L >> 2);
        const int jb = wn * 64 + ((L & 3) << 1);
#pragma unroll
        for (int mt = 0; mt < 2; mt++) {
#pragma unroll
            for (int nt = 0; nt < 8; nt++) {
                const float* c = acc[mt][nt];
                int p = pb + mt * 16;
                int j = jb + nt * 8;
                yt[j * 132 + p] = c[0];
                yt[(j + 1) * 132 + p] = c[1];
                yt[j * 132 + p + 8] = c[2];
                yt[(j + 1) * 132 + p + 8] = c[3];
            }
        }
    }
    __syncthreads();

    const int blk2 = srcb * NPTILE + pt;
#pragma unroll 1
    for (int rr = 0; rr < 16; rr++) {
        int j = wid * 16 + rr;
        float blj = __ldg(bl + j);
        float4 v = *reinterpret_cast<const float4*>(yt + j * 132 + L * 4);
        v.x += blj; v.y += blj; v.z += blj; v.w += blj;
        *reinterpret_cast<float4*>(
            g_Yt + ((size_t)srcb * Cq + j) * Pq + pt * 128 + L * 4) = v;
        float ls = (v.x + v.y) + (v.z + v.w);
        float lq = (v.x * v.x + v.y * v.y) + (v.z * v.z + v.w * v.w);
#pragma unroll
        for (int o = 16; o > 0; o >>= 1) {
            ls += __shfl_xor_sync(0xFFFFFFFFu, ls, o);
            lq += __shfl_xor_sync(0xFFFFFFFFu, lq, o);
        }
        if (L == 0) {
            g_ps[(size_t)blk2 * Cq + j] = ls;
            g_pq[(size_t)blk2 * Cq + j] = lq;
        }
    }
}

// ============================================================
// stats (two stage, multiplicity-weighted, deterministic)
// ============================================================
__global__ void stats1_kernel() {
    int j = threadIdx.x;
    int r0 = blockIdx.x * (NBLK2 / 32);
    float s = 0.f, q = 0.f;
    for (int r = 0; r < NBLK2 / 32; r++) {
        int row = r0 + r;
        float w = (float)g_cnt[row >> 5];
        s += w * g_ps[(size_t)row * Cq + j];
        q += w * g_pq[(size_t)row * Cq + j];
    }
    g_ps2[blockIdx.x * Cq + j] = s;
    g_pq2[blockIdx.x * Cq + j] = q;
}

__global__ void stats2_kernel(const float* __restrict__ gamma,
                              const float* __restrict__ beta) {
    int j = threadIdx.x;
    float s = 0.f, q = 0.f;
#pragma unroll
    for (int r = 0; r < 32; r++) {
        s += g_ps2[r * Cq + j];
        q += g_pq2[r * Cq + j];
    }
    const float inv = 1.0f / (float)(Bq * Pq);
    float mean = s * inv;
    float var = q * inv - mean * mean;
    float sc = rsqrtf(var + EPSq) * gamma[j];
    g_scale[j] = sc;
    g_shift[j] = beta[j] - mean * sc;
}

// ============================================================
// out: scale+shift+relu, pure coalesced copy (Y already [s][j][p])
// ============================================================
__global__ __launch_bounds__(256) void out_kernel(float* __restrict__ out,
                                                  const int* __restrict__ didx) {
    const int b = blockIdx.x >> 7;
    const int j = blockIdx.x & 127;
    const int src = didx[b];
    const float sc = g_scale[j];
    const float sh = g_shift[j];
    const float4* in = reinterpret_cast<const float4*>(
        g_Yt + ((size_t)src * Cq + j) * Pq);
    float4* op = reinterpret_cast<float4*>(out + (size_t)blockIdx.x * Pq);
#pragma unroll
    for (int k = 0; k < 4; k++) {
        int idx = threadIdx.x + k * 256;
        float4 v = in[idx];
        v.x = fmaxf(fmaf(v.x, sc, sh), 0.f);
        v.y = fmaxf(fmaf(v.y, sc, sh), 0.f);
        v.z = fmaxf(fmaf(v.z, sc, sh), 0.f);
        v.w = fmaxf(fmaf(v.w, sc, sh), 0.f);
        op[idx] = v;
    }
}

// ============================================================
// Launch
// ============================================================
extern "C" void kernel_launch(void* const* d_in, const int* in_sizes, int n_in,
                              void* d_out, int out_size) {
    const float* xyz    = (const float*)d_in[0];
    const float* points = (const float*)d_in[1];
    const float* lc     = (const float*)d_in[2];
    const int*   nbr    = (const int*)d_in[3];
    const int*   didx   = (const int*)d_in[4];
    const float* Ww     = (const float*)d_in[5];
    const float* bw     = (const float*)d_in[6];
    const float* Wl     = (const float*)d_in[7];
    const float* bl     = (const float*)d_in[8];
    const float* gamma  = (const float*)d_in[9];
    const float* beta   = (const float*)d_in[10];
    float* out = (float*)d_out;

    cudaMemcpyAsync(out, xyz, (size_t)Bq * Pq * 3 * sizeof(float),
                    cudaMemcpyDeviceToDevice, 0);

    cudaFuncSetAttribute(gemm_kernel,
                         cudaFuncAttributeMaxDynamicSharedMemorySize, GSM_TOTAL);

    prep_kernel<<<256, 256>>>(Ww, bw, Wl, didx);

    dim3 gg(GBLK_PER_B, Bq);
    gather_kernel<<<gg, 128>>>(points, lc, nbr);

    dim3 g2(NPTILE, Bq);
    gemm_kernel<<<g2, 256, GSM_TOTAL>>>(bl);

    stats1_kernel<<<32, Cq>>>();
    stats2_kernel<<<1, Cq>>>(gamma, beta);

    out_kernel<<<Bq * Cq, 256>>>(out + (size_t)Bq * Pq * 3, didx);
}

// round 6
// speedup vs baseline: 3.3641x; 1.1150x over previous
#include <cuda_runtime.h>
#include <cuda_bf16.h>
#include <cuda_fp16.h>
#include <cstdint>
#include <cstddef>

// Problem constants
#define Bq 8
#define Nq 4096
#define Pq 4096
#define Kq 32
#define Cq 128
#define Wq 16
#define EPSq 1e-5f

#define TPT 16                        // points per gather block
#define GBLK_PER_B (Pq / TPT)         // 256
#define NPTILE (Pq / 128)             // 32 p-tiles per batch
#define NBLK2 (Bq * NPTILE)           // 256 GEMM blocks

// ------------------- device globals (no allocation allowed) -------------------
__device__ __align__(256) __half g_Ph[(size_t)Bq * Nq * Cq];           // fp16 points
__device__ __align__(256) __nv_bfloat16 g_Shi[(size_t)Bq * Pq * 512];  // [s][p][i]
__device__ __align__(256) __nv_bfloat16 g_Slo[(size_t)Bq * Pq * 512];
__device__ __align__(256) __nv_bfloat16 g_Ahi[128 * 512];              // [j][i]
__device__ __align__(256) __nv_bfloat16 g_Alo[128 * 512];
__device__ float g_Yt[(size_t)Bq * Cq * Pq];                           // [s][j][p]
__device__ float g_ps[NBLK2 * Cq];
__device__ float g_pq[NBLK2 * Cq];
__device__ float g_scale[Cq];
__device__ float g_shift[Cq];
__device__ int   g_cnt[Bq];

// ------------------- helpers -------------------
__device__ __forceinline__ unsigned long long pk2(float x, float y) {
    unsigned long long r;
    asm("mov.b64 %0, {%1,%2};" : "=l"(r) : "f"(x), "f"(y));
    return r;
}
__device__ __forceinline__ void fma2(unsigned long long& d,
                                     unsigned long long a,
                                     unsigned long long b) {
    asm("fma.rn.f32x2 %0, %1, %2, %0;" : "+l"(d) : "l"(a), "l"(b));
}
__device__ __forceinline__ float2 up2(unsigned long long v) {
    float x, y;
    asm("mov.b64 {%0,%1}, %2;" : "=f"(x), "=f"(y) : "l"(v));
    return make_float2(x, y);
}
__device__ __forceinline__ uint32_t smem_to_u32(const void* p) {
    uint32_t a;
    asm("{ .reg .u64 t; cvta.to.shared.u64 t, %1; cvt.u32.u64 %0, t; }"
        : "=r"(a) : "l"(p));
    return a;
}

#define CP_ASYNC16(dst, src) \
    asm volatile("cp.async.cg.shared.global [%0], [%1], 16;" \
                 :: "r"(dst), "l"(src) : "memory")
#define CP_COMMIT() asm volatile("cp.async.commit_group;" ::: "memory")
#define CP_WAIT(n)  asm volatile("cp.async.wait_group %0;" :: "n"(n) : "memory")

__device__ __forceinline__ void ldsm_x4(uint32_t addr, uint32_t* r) {
    asm volatile("ldmatrix.sync.aligned.m8n8.x4.shared.b16 {%0,%1,%2,%3}, [%4];"
                 : "=r"(r[0]), "=r"(r[1]), "=r"(r[2]), "=r"(r[3]) : "r"(addr));
}
__device__ __forceinline__ void mma_bf16(float* c, const uint32_t* a,
                                         uint32_t b0, uint32_t b1) {
    asm volatile(
        "mma.sync.aligned.m16n8k16.row.col.f32.bf16.bf16.f32 "
        "{%0,%1,%2,%3}, {%4,%5,%6,%7}, {%8,%9}, {%0,%1,%2,%3};"
        : "+f"(c[0]), "+f"(c[1]), "+f"(c[2]), "+f"(c[3])
        : "r"(a[0]), "r"(a[1]), "r"(a[2]), "r"(a[3]), "r"(b0), "r"(b1));
}

// ============================================================
// prep: A'[i=d*128+c][j] -> bf16 hi/lo, transposed to [j][i]; batch counts
// ============================================================
__global__ void prep_kernel(const float* __restrict__ Ww,
                            const float* __restrict__ bw,
                            const float* __restrict__ Wl,
                            const int* __restrict__ didx) {
    int idx = blockIdx.x * blockDim.x + threadIdx.x;
    if (blockIdx.x == 0 && threadIdx.x < Bq) {
        int c = 0;
#pragma unroll
        for (int b = 0; b < Bq; b++) c += (didx[b] == (int)threadIdx.x);
        g_cnt[threadIdx.x] = c;
    }
    if (idx >= 4 * Cq * Cq) return;
    int d = idx >> 14;
    int c = (idx >> 7) & (Cq - 1);
    int j = idx & (Cq - 1);
    float acc = 0.f;
#pragma unroll
    for (int w = 0; w < Wq; w++) {
        float coef = (d < 3) ? Ww[d * Wq + w] : bw[w];
        acc = fmaf(coef, Wl[(c * Wq + w) * Cq + j], acc);
    }
    int i = (d << 7) | c;
    __nv_bfloat16 h = __float2bfloat16_rn(acc);
    __nv_bfloat16 l = __float2bfloat16_rn(acc - __bfloat162float(h));
    g_Ahi[(size_t)j * 512 + i] = h;
    g_Alo[(size_t)j * 512 + i] = l;
}

// ============================================================
// convert: points fp32 -> fp16 (halves gather read traffic)
// ============================================================
__global__ __launch_bounds__(256) void convert_kernel(const float* __restrict__ points) {
    size_t idx = ((size_t)blockIdx.x * 256 + threadIdx.x) * 4;
    float4 v = *reinterpret_cast<const float4*>(points + idx);
    __half2 h0 = __floats2half2_rn(v.x, v.y);
    __half2 h1 = __floats2half2_rn(v.z, v.w);
    *reinterpret_cast<__half2*>(g_Ph + idx) = h0;
    *reinterpret_cast<__half2*>(g_Ph + idx + 2) = h1;
}

// ============================================================
// gather: S[p,i] = sum_k coef[k,d] * points_h[s, nbr[k], c]
//   128 thr; thread handles channel pair (2c2, 2c2+1) of point 2*t8+h
// ============================================================
__global__ __launch_bounds__(128, 8) void gather_kernel(
    const float* __restrict__ lc,
    const int* __restrict__ nbr) {
    __shared__ ulonglong2 s_L[TPT][Kq];
    __shared__ uint32_t s_off[TPT][Kq];

    const int tid = threadIdx.x;
    const int s = blockIdx.y;
    if (g_cnt[s] == 0) return;
    const int p0 = blockIdx.x * TPT;
    const size_t base = ((size_t)s * Pq + p0) * Kq;

    for (int i = tid; i < TPT * Kq; i += 128) {
        int t = i >> 5, k = i & 31;
        s_off[t][k] = (uint32_t)nbr[base + (size_t)t * Kq + k] << 8;   // *256B row
        const float* Lp = lc + (base + (size_t)t * Kq + k) * 3;
        s_L[t][k] = make_ulonglong2(pk2(Lp[0], Lp[1]), pk2(Lp[2], 1.0f));
    }
    __syncthreads();

    const int h = tid >> 6, c2 = tid & 63;
    const char* ptsb = (const char*)(g_Ph + (size_t)s * Nq * Cq) + 4 * c2;

#pragma unroll 1
    for (int t8 = 0; t8 < 8; t8++) {
        const int t = t8 * 2 + h;
        unsigned long long e01 = 0ull, e23 = 0ull, o01 = 0ull, o23 = 0ull;
#pragma unroll
        for (int k = 0; k < Kq; k++) {
            __half2 hv = *reinterpret_cast<const __half2*>(ptsb + s_off[t][k]);
            float2 v = __half22float2(hv);
            ulonglong2 L = s_L[t][k];
            unsigned long long vx = pk2(v.x, v.x), vy = pk2(v.y, v.y);
            fma2(e01, vx, L.x);
            fma2(e23, vx, L.y);
            fma2(o01, vy, L.x);
            fma2(o23, vy, L.y);
        }
        float2 fe01 = up2(e01), fe23 = up2(e23);
        float2 fo01 = up2(o01), fo23 = up2(o23);
        const size_t rb = ((size_t)s * Pq + p0 + t) * 512;
        float ev[4] = {fe01.x, fe01.y, fe23.x, fe23.y};
        float ov[4] = {fo01.x, fo01.y, fo23.x, fo23.y};
#pragma unroll
        for (int d = 0; d < 4; d++) {
            __nv_bfloat16 he = __float2bfloat16_rn(ev[d]);
            __nv_bfloat16 le = __float2bfloat16_rn(ev[d] - __bfloat162float(he));
            __nv_bfloat16 ho = __float2bfloat16_rn(ov[d]);
            __nv_bfloat16 lo = __float2bfloat16_rn(ov[d] - __bfloat162float(ho));
            *reinterpret_cast<__nv_bfloat162*>(g_Shi + rb + d * 128 + 2 * c2) =
                __nv_bfloat162(he, ho);
            *reinterpret_cast<__nv_bfloat162*>(g_Slo + rb + d * 128 + 2 * c2) =
                __nv_bfloat162(le, lo);
        }
    }
}

// ============================================================
// GEMM: Y[p,j] = S[p,i] * A'[j,i]^T  via mma.sync bf16 hi/lo split
// ============================================================
#define TILE_B 10240                 // 128 rows * 80B
#define OFF_SHI 0
#define OFF_SLO (TILE_B)
#define OFF_AHI (2 * TILE_B)
#define OFF_ALO (3 * TILE_B)
#define BUF_B (4 * TILE_B)           // 40960
#define GSM_TOTAL (2 * BUF_B)        // 81920

__global__ __launch_bounds__(256, 2) void gemm_kernel(const float* __restrict__ bl) {
    extern __shared__ __align__(128) char sm[];
    const int tid = threadIdx.x;
    const int wid = tid >> 5;
    const int L = tid & 31;
    const int srcb = blockIdx.y;
    if (g_cnt[srcb] == 0) return;
    const int pt = blockIdx.x;
    const int wm = wid >> 1;     // 0..3  (p dim)
    const int wn = wid & 1;      // 0..1  (j dim)

    const uint32_t smb = smem_to_u32(sm);
    const __nv_bfloat16* Shi = g_Shi + ((size_t)srcb * Pq + pt * 128) * 512;
    const __nv_bfloat16* Slo = g_Slo + ((size_t)srcb * Pq + pt * 128) * 512;

    const int r0c = tid >> 2, seg0 = tid & 3;

    float acc[2][8][4];
#pragma unroll
    for (int mt = 0; mt < 2; mt++)
#pragma unroll
        for (int nt = 0; nt < 8; nt++)
#pragma unroll
            for (int q = 0; q < 4; q++) acc[mt][nt][q] = 0.f;

    const int grp = L >> 3, lr = L & 7;
    const uint32_t aRow = (uint32_t)(wm * 32 + (grp & 1) * 8 + lr) * 80
                        + (uint32_t)(grp >> 1) * 16;
    const uint32_t bRow = (uint32_t)(wn * 64 + (grp >> 1) * 8 + lr) * 80
                        + (uint32_t)(grp & 1) * 16;

#define ISSUE(kc, buf) do {                                                     \
        uint32_t bb = smb + (buf) * BUF_B;                                      \
        _Pragma("unroll")                                                       \
        for (int ii = 0; ii < 2; ii++) {                                        \
            int rr = r0c + ii * 64;                                             \
            uint32_t dsto = (uint32_t)rr * 80 + (uint32_t)seg0 * 16;            \
            size_t go = (size_t)rr * 512 + (size_t)(kc) * 32 + seg0 * 8;        \
            CP_ASYNC16(bb + OFF_SHI + dsto, (const char*)(Shi + go));           \
            CP_ASYNC16(bb + OFF_SLO + dsto, (const char*)(Slo + go));           \
            CP_ASYNC16(bb + OFF_AHI + dsto, (const char*)(g_Ahi + go));         \
            CP_ASYNC16(bb + OFF_ALO + dsto, (const char*)(g_Alo + go));         \
        }                                                                       \
        CP_COMMIT();                                                            \
    } while (0)

    ISSUE(0, 0);

#pragma unroll 1
    for (int kc = 0; kc < 16; kc++) {
        if (kc < 15) { ISSUE(kc + 1, (kc + 1) & 1); CP_WAIT(1); }
        else         { CP_WAIT(0); }
        __syncthreads();

        const uint32_t bb = smb + (kc & 1) * BUF_B;
#pragma unroll
        for (int ks = 0; ks < 2; ks++) {
            uint32_t ah[2][4], al[2][4];
#pragma unroll
            for (int mt = 0; mt < 2; mt++) {
                uint32_t ao = aRow + (uint32_t)mt * (16 * 80) + (uint32_t)ks * 32;
                ldsm_x4(bb + OFF_SHI + ao, ah[mt]);
                ldsm_x4(bb + OFF_SLO + ao, al[mt]);
            }
#pragma unroll
            for (int ng = 0; ng < 4; ng++) {
                uint32_t bh[4], blo[4];
                uint32_t bo = bRow + (uint32_t)ng * (16 * 80) + (uint32_t)ks * 32;
                ldsm_x4(bb + OFF_AHI + bo, bh);
                ldsm_x4(bb + OFF_ALO + bo, blo);
#pragma unroll
                for (int mt = 0; mt < 2; mt++) {
#pragma unroll
                    for (int t2 = 0; t2 < 2; t2++) {
                        float* c = acc[mt][2 * ng + t2];
                        mma_bf16(c, ah[mt], bh[2 * t2], bh[2 * t2 + 1]);
                        mma_bf16(c, ah[mt], blo[2 * t2], blo[2 * t2 + 1]);
                        mma_bf16(c, al[mt], bh[2 * t2], bh[2 * t2 + 1]);
                    }
                }
            }
        }
        __syncthreads();
    }

    // ---- epilogue: C frags -> smem [j][132] -> coalesced Y + LN partials ----
    float* yt = (float*)sm;
    {
        const int pb = wm * 32 + (L >> 2);
        const int jb = wn * 64 + ((L & 3) << 1);
#pragma unroll
        for (int mt = 0; mt < 2; mt++) {
#pragma unroll
            for (int nt = 0; nt < 8; nt++) {
                const float* c = acc[mt][nt];
                int p = pb + mt * 16;
                int j = jb + nt * 8;
                yt[j * 132 + p] = c[0];
                yt[(j + 1) * 132 + p] = c[1];
                yt[j * 132 + p + 8] = c[2];
                yt[(j + 1) * 132 + p + 8] = c[3];
            }
        }
    }
    __syncthreads();

    const int blk2 = srcb * NPTILE + pt;
#pragma unroll 1
    for (int rr = 0; rr < 16; rr++) {
        int j = wid * 16 + rr;
        float blj = __ldg(bl + j);
        float4 v = *reinterpret_cast<const float4*>(yt + j * 132 + L * 4);
        v.x += blj; v.y += blj; v.z += blj; v.w += blj;
        *reinterpret_cast<float4*>(
            g_Yt + ((size_t)srcb * Cq + j) * Pq + pt * 128 + L * 4) = v;
        float ls = (v.x + v.y) + (v.z + v.w);
        float lq = (v.x * v.x + v.y * v.y) + (v.z * v.z + v.w * v.w);
#pragma unroll
        for (int o = 16; o > 0; o >>= 1) {
            ls += __shfl_xor_sync(0xFFFFFFFFu, ls, o);
            lq += __shfl_xor_sync(0xFFFFFFFFu, lq, o);
        }
        if (L == 0) {
            g_ps[(size_t)blk2 * Cq + j] = ls;
            g_pq[(size_t)blk2 * Cq + j] = lq;
        }
    }
}

// ============================================================
// stats: single-block deterministic multiplicity-weighted reduction
// ============================================================
__global__ __launch_bounds__(1024) void stats_kernel(const float* __restrict__ gamma,
                                                     const float* __restrict__ beta) {
    __shared__ float ss[8][Cq], sq[8][Cq];
    const int j = threadIdx.x & 127;
    const int g = threadIdx.x >> 7;   // 0..7
    float s = 0.f, q = 0.f;
    for (int r = g; r < NBLK2; r += 8) {
        float w = (float)g_cnt[r >> 5];
        s += w * g_ps[(size_t)r * Cq + j];
        q += w * g_pq[(size_t)r * Cq + j];
    }
    ss[g][j] = s;
    sq[g][j] = q;
    __syncthreads();
    if (g == 0) {
        float S = 0.f, Q = 0.f;
#pragma unroll
        for (int i = 0; i < 8; i++) { S += ss[i][j]; Q += sq[i][j]; }
        const float inv = 1.0f / (float)(Bq * Pq);
        float mean = S * inv;
        float var = Q * inv - mean * mean;
        float sc = rsqrtf(var + EPSq) * gamma[j];
        g_scale[j] = sc;
        g_shift[j] = beta[j] - mean * sc;
    }
}

// ============================================================
// out: scale+shift+relu, pure coalesced copy (Y already [s][j][p])
// ============================================================
__global__ __launch_bounds__(256) void out_kernel(float* __restrict__ out,
                                                  const int* __restrict__ didx) {
    const int b = blockIdx.x >> 7;
    const int j = blockIdx.x & 127;
    const int src = didx[b];
    const float sc = g_scale[j];
    const float sh = g_shift[j];
    const float4* in = reinterpret_cast<const float4*>(
        g_Yt + ((size_t)src * Cq + j) * Pq);
    float4* op = reinterpret_cast<float4*>(out + (size_t)blockIdx.x * Pq);
#pragma unroll
    for (int k = 0; k < 4; k++) {
        int idx = threadIdx.x + k * 256;
        float4 v = in[idx];
        v.x = fmaxf(fmaf(v.x, sc, sh), 0.f);
        v.y = fmaxf(fmaf(v.y, sc, sh), 0.f);
        v.z = fmaxf(fmaf(v.z, sc, sh), 0.f);
        v.w = fmaxf(fmaf(v.w, sc, sh), 0.f);
        op[idx] = v;
    }
}

// ============================================================
// Launch
// ============================================================
extern "C" void kernel_launch(void* const* d_in, const int* in_sizes, int n_in,
                              void* d_out, int out_size) {
    const float* xyz    = (const float*)d_in[0];
    const float* points = (const float*)d_in[1];
    const float* lc     = (const float*)d_in[2];
    const int*   nbr    = (const int*)d_in[3];
    const int*   didx   = (const int*)d_in[4];
    const float* Ww     = (const float*)d_in[5];
    const float* bw     = (const float*)d_in[6];
    const float* Wl     = (const float*)d_in[7];
    const float* bl     = (const float*)d_in[8];
    const float* gamma  = (const float*)d_in[9];
    const float* beta   = (const float*)d_in[10];
    float* out = (float*)d_out;

    cudaMemcpyAsync(out, xyz, (size_t)Bq * Pq * 3 * sizeof(float),
                    cudaMemcpyDeviceToDevice, 0);

    cudaFuncSetAttribute(gemm_kernel,
                         cudaFuncAttributeMaxDynamicSharedMemorySize, GSM_TOTAL);

    prep_kernel<<<256, 256>>>(Ww, bw, Wl, didx);
    convert_kernel<<<(Bq * Nq * Cq) / 1024, 256>>>(points);

    dim3 gg(GBLK_PER_B, Bq);
    gather_kernel<<<gg, 128>>>(lc, nbr);

    dim3 g2(NPTILE, Bq);
    gemm_kernel<<<g2, 256, GSM_TOTAL>>>(bl);

    stats_kernel<<<1, 1024>>>(gamma, beta);

    out_kernel<<<Bq * Cq, 256>>>(out + (size_t)Bq * Pq * 3, didx);
}

// round 7
// speedup vs baseline: 4.3086x; 1.2808x over previous
#include <cuda_runtime.h>
#include <cuda_bf16.h>
#include <cuda_fp16.h>
#include <cstdint>
#include <cstddef>

// Problem constants
#define Bq 8
#define Nq 4096
#define Pq 4096
#define Kq 32
#define Cq 128
#define Wq 16
#define EPSq 1e-5f

#define TPT 16                        // points per gather block
#define GBLK_PER_B (Pq / TPT)         // 256
#define NPTILE (Pq / 128)             // 32 p-tiles per batch
#define NBLK2 (Bq * NPTILE)           // 256 stat rows

// ------------------- device globals (no allocation allowed) -------------------
__device__ __align__(256) __half g_Ph[(size_t)Bq * Nq * Cq];     // fp16 points
__device__ __align__(256) __half g_S[(size_t)Bq * Pq * 512];     // fp16 S, [s][p][i]
__device__ __align__(256) __half g_Ahf[128 * 512];               // A' hi fp16, [j][i]
__device__ __align__(256) __half g_Alf[128 * 512];               // A' lo fp16
__device__ float g_Yt[(size_t)Bq * Cq * Pq];                     // [s][j][p]
__device__ float g_ps[NBLK2 * Cq];
__device__ float g_pq[NBLK2 * Cq];
__device__ float g_scale[Cq];
__device__ float g_shift[Cq];
__device__ int   g_cnt[Bq];

// ------------------- helpers -------------------
__device__ __forceinline__ unsigned long long pk2(float x, float y) {
    unsigned long long r;
    asm("mov.b64 %0, {%1,%2};" : "=l"(r) : "f"(x), "f"(y));
    return r;
}
__device__ __forceinline__ void fma2(unsigned long long& d,
                                     unsigned long long a,
                                     unsigned long long b) {
    asm("fma.rn.f32x2 %0, %1, %2, %0;" : "+l"(d) : "l"(a), "l"(b));
}
__device__ __forceinline__ float2 up2(unsigned long long v) {
    float x, y;
    asm("mov.b64 {%0,%1}, %2;" : "=f"(x), "=f"(y) : "l"(v));
    return make_float2(x, y);
}
__device__ __forceinline__ uint32_t smem_to_u32(const void* p) {
    uint32_t a;
    asm("{ .reg .u64 t; cvta.to.shared.u64 t, %1; cvt.u32.u64 %0, t; }"
        : "=r"(a) : "l"(p));
    return a;
}

#define CP_ASYNC16(dst, src) \
    asm volatile("cp.async.cg.shared.global [%0], [%1], 16;" \
                 :: "r"(dst), "l"(src) : "memory")
#define CP_COMMIT() asm volatile("cp.async.commit_group;" ::: "memory")
#define CP_WAIT(n)  asm volatile("cp.async.wait_group %0;" :: "n"(n) : "memory")

__device__ __forceinline__ void ldsm_x4(uint32_t addr, uint32_t* r) {
    asm volatile("ldmatrix.sync.aligned.m8n8.x4.shared.b16 {%0,%1,%2,%3}, [%4];"
                 : "=r"(r[0]), "=r"(r[1]), "=r"(r[2]), "=r"(r[3]) : "r"(addr));
}
__device__ __forceinline__ void mma_f16(float* c, const uint32_t* a,
                                        uint32_t b0, uint32_t b1) {
    asm volatile(
        "mma.sync.aligned.m16n8k16.row.col.f32.f16.f16.f32 "
        "{%0,%1,%2,%3}, {%4,%5,%6,%7}, {%8,%9}, {%0,%1,%2,%3};"
        : "+f"(c[0]), "+f"(c[1]), "+f"(c[2]), "+f"(c[3])
        : "r"(a[0]), "r"(a[1]), "r"(a[2]), "r"(a[3]), "r"(b0), "r"(b1));
}

// ============================================================
// prep: A'[i=d*128+c][j] -> fp16 hi/lo, transposed to [j][i]; batch counts
// ============================================================
__global__ void prep_kernel(const float* __restrict__ Ww,
                            const float* __restrict__ bw,
                            const float* __restrict__ Wl,
                            const int* __restrict__ didx) {
    int idx = blockIdx.x * blockDim.x + threadIdx.x;
    if (blockIdx.x == 0 && threadIdx.x < Bq) {
        int c = 0;
#pragma unroll
        for (int b = 0; b < Bq; b++) c += (didx[b] == (int)threadIdx.x);
        g_cnt[threadIdx.x] = c;
    }
    if (idx >= 4 * Cq * Cq) return;
    int d = idx >> 14;
    int c = (idx >> 7) & (Cq - 1);
    int j = idx & (Cq - 1);
    float acc = 0.f;
#pragma unroll
    for (int w = 0; w < Wq; w++) {
        float coef = (d < 3) ? Ww[d * Wq + w] : bw[w];
        acc = fmaf(coef, Wl[(c * Wq + w) * Cq + j], acc);
    }
    int i = (d << 7) | c;
    __half h = __float2half_rn(acc);
    __half l = __float2half_rn(acc - __half2float(h));
    g_Ahf[(size_t)j * 512 + i] = h;
    g_Alf[(size_t)j * 512 + i] = l;
}

// ============================================================
// convert: points fp32 -> fp16
// ============================================================
__global__ __launch_bounds__(256) void convert_kernel(const float* __restrict__ points) {
    size_t idx = ((size_t)blockIdx.x * 256 + threadIdx.x) * 4;
    float4 v = *reinterpret_cast<const float4*>(points + idx);
    *reinterpret_cast<__half2*>(g_Ph + idx) = __floats2half2_rn(v.x, v.y);
    *reinterpret_cast<__half2*>(g_Ph + idx + 2) = __floats2half2_rn(v.z, v.w);
}

// ============================================================
// gather: S[p,i] = sum_k coef[k,d] * points_h[s, nbr[k], c]; emit fp16
// ============================================================
__global__ __launch_bounds__(128, 8) void gather_kernel(
    const float* __restrict__ lc,
    const int* __restrict__ nbr) {
    __shared__ ulonglong2 s_L[TPT][Kq];
    __shared__ uint32_t s_off[TPT][Kq];

    const int tid = threadIdx.x;
    const int s = blockIdx.y;
    if (g_cnt[s] == 0) return;
    const int p0 = blockIdx.x * TPT;
    const size_t base = ((size_t)s * Pq + p0) * Kq;

    for (int i = tid; i < TPT * Kq; i += 128) {
        int t = i >> 5, k = i & 31;
        s_off[t][k] = (uint32_t)nbr[base + (size_t)t * Kq + k] << 8;   // *256B row
        const float* Lp = lc + (base + (size_t)t * Kq + k) * 3;
        s_L[t][k] = make_ulonglong2(pk2(Lp[0], Lp[1]), pk2(Lp[2], 1.0f));
    }
    __syncthreads();

    const int h = tid >> 6, c2 = tid & 63;
    const char* ptsb = (const char*)(g_Ph + (size_t)s * Nq * Cq) + 4 * c2;

#pragma unroll 1
    for (int t8 = 0; t8 < 8; t8++) {
        const int t = t8 * 2 + h;
        unsigned long long e01 = 0ull, e23 = 0ull, o01 = 0ull, o23 = 0ull;
#pragma unroll
        for (int k = 0; k < Kq; k++) {
            __half2 hv = *reinterpret_cast<const __half2*>(ptsb + s_off[t][k]);
            float2 v = __half22float2(hv);
            ulonglong2 L = s_L[t][k];
            unsigned long long vx = pk2(v.x, v.x), vy = pk2(v.y, v.y);
            fma2(e01, vx, L.x);
            fma2(e23, vx, L.y);
            fma2(o01, vy, L.x);
            fma2(o23, vy, L.y);
        }
        float2 fe01 = up2(e01), fe23 = up2(e23);
        float2 fo01 = up2(o01), fo23 = up2(o23);
        const size_t rb = ((size_t)s * Pq + p0 + t) * 512;
        float ev[4] = {fe01.x, fe01.y, fe23.x, fe23.y};
        float ov[4] = {fo01.x, fo01.y, fo23.x, fo23.y};
#pragma unroll
        for (int d = 0; d < 4; d++) {
            *reinterpret_cast<__half2*>(g_S + rb + d * 128 + 2 * c2) =
                __floats2half2_rn(ev[d], ov[d]);
        }
    }
}

// ============================================================
// GEMM: Y[p,j] = S[p,i] * (A'hi + A'lo)[j,i]^T  via mma.sync fp16
//   block tile: 128p x 64j, K chunks of 32; grid 512
//   smem rows: 32 fp16 = 64B data padded to 80B (conflict-free ldmatrix)
// ============================================================
#define STILE_B 10240                // 128 rows * 80B
#define ATILE_B 5120                 // 64 rows * 80B
#define OFF_S   0
#define OFF_AHI (STILE_B)
#define OFF_ALO (STILE_B + ATILE_B)
#define BUF_B   (STILE_B + 2 * ATILE_B)   // 20480
#define GSM_TOTAL (2 * BUF_B)             // 40960 (epilogue: 64*132*4=33792 fits)

__global__ __launch_bounds__(256, 3) void gemm_kernel(const float* __restrict__ bl) {
    extern __shared__ __align__(128) char sm[];
    const int tid = threadIdx.x;
    const int wid = tid >> 5;
    const int L = tid & 31;
    const int srcb = blockIdx.y;
    if (g_cnt[srcb] == 0) return;
    const int pt = blockIdx.x >> 1;
    const int jh = blockIdx.x & 1;     // which 64-j half
    const int wm = wid >> 1;           // 0..3  (p dim, 32 each)
    const int wn = wid & 1;            // 0..1  (j dim, 32 each)

    const uint32_t smb = smem_to_u32(sm);
    const __half* Sp = g_S + ((size_t)srcb * Pq + pt * 128) * 512;
    const __half* Ah = g_Ahf + (size_t)(jh * 64) * 512;
    const __half* Al = g_Alf + (size_t)(jh * 64) * 512;

    const int r0c = tid >> 2, seg0 = tid & 3;    // copy mapping

    float acc[2][4][4];
#pragma unroll
    for (int mt = 0; mt < 2; mt++)
#pragma unroll
        for (int nt = 0; nt < 4; nt++)
#pragma unroll
            for (int q = 0; q < 4; q++) acc[mt][nt][q] = 0.f;

    const int grp = L >> 3, lr = L & 7;
    const uint32_t aRow = (uint32_t)(wm * 32 + (grp & 1) * 8 + lr) * 80
                        + (uint32_t)(grp >> 1) * 16;
    const uint32_t bRow = (uint32_t)(wn * 32 + (grp >> 1) * 8 + lr) * 80
                        + (uint32_t)(grp & 1) * 16;

#define ISSUE(kc, buf) do {                                                     \
        uint32_t bb = smb + (buf) * BUF_B;                                      \
        size_t ko = (size_t)(kc) * 32 + seg0 * 8;                               \
        uint32_t dsto = (uint32_t)r0c * 80 + (uint32_t)seg0 * 16;               \
        CP_ASYNC16(bb + OFF_S + dsto, (const char*)(Sp + (size_t)r0c * 512 + ko)); \
        CP_ASYNC16(bb + OFF_S + dsto + 64 * 80,                                 \
                   (const char*)(Sp + (size_t)(r0c + 64) * 512 + ko));          \
        CP_ASYNC16(bb + OFF_AHI + dsto, (const char*)(Ah + (size_t)r0c * 512 + ko)); \
        CP_ASYNC16(bb + OFF_ALO + dsto, (const char*)(Al + (size_t)r0c * 512 + ko)); \
        CP_COMMIT();                                                            \
    } while (0)

    ISSUE(0, 0);

#pragma unroll 1
    for (int kc = 0; kc < 16; kc++) {
        if (kc < 15) { ISSUE(kc + 1, (kc + 1) & 1); CP_WAIT(1); }
        else         { CP_WAIT(0); }
        __syncthreads();

        const uint32_t bb = smb + (kc & 1) * BUF_B;
#pragma unroll
        for (int ks = 0; ks < 2; ks++) {
            uint32_t af[2][4];
#pragma unroll
            for (int mt = 0; mt < 2; mt++) {
                uint32_t ao = aRow + (uint32_t)mt * (16 * 80) + (uint32_t)ks * 32;
                ldsm_x4(bb + OFF_S + ao, af[mt]);
            }
#pragma unroll
            for (int ng = 0; ng < 2; ng++) {
                uint32_t bh[4], bl2[4];
                uint32_t bo = bRow + (uint32_t)ng * (16 * 80) + (uint32_t)ks * 32;
                ldsm_x4(bb + OFF_AHI + bo, bh);
                ldsm_x4(bb + OFF_ALO + bo, bl2);
#pragma unroll
                for (int mt = 0; mt < 2; mt++) {
#pragma unroll
                    for (int t2 = 0; t2 < 2; t2++) {
                        float* c = acc[mt][2 * ng + t2];
                        mma_f16(c, af[mt], bh[2 * t2], bh[2 * t2 + 1]);
                        mma_f16(c, af[mt], bl2[2 * t2], bl2[2 * t2 + 1]);
                    }
                }
            }
        }
        __syncthreads();
    }

    // ---- epilogue: C frags -> smem [64j][132] -> coalesced Y + LN partials ----
    float* yt = (float*)sm;
    {
        const int pb = wm * 32 + (L >> 2);
        const int jb = wn * 32 + ((L & 3) << 1);
#pragma unroll
        for (int mt = 0; mt < 2; mt++) {
#pragma unroll
            for (int nt = 0; nt < 4; nt++) {
                const float* c = acc[mt][nt];
                int p = pb + mt * 16;
                int j = jb + nt * 8;
                yt[j * 132 + p] = c[0];
                yt[(j + 1) * 132 + p] = c[1];
                yt[j * 132 + p + 8] = c[2];
                yt[(j + 1) * 132 + p + 8] = c[3];
            }
        }
    }
    __syncthreads();

    const int blk2 = srcb * NPTILE + pt;
#pragma unroll 1
    for (int rr = 0; rr < 8; rr++) {
        int j = wid * 8 + rr;          // local j in [0,64)
        int jg = jh * 64 + j;          // global output channel
        float blj = __ldg(bl + jg);
        float4 v = *reinterpret_cast<const float4*>(yt + j * 132 + L * 4);
        v.x += blj; v.y += blj; v.z += blj; v.w += blj;
        *reinterpret_cast<float4*>(
            g_Yt + ((size_t)srcb * Cq + jg) * Pq + pt * 128 + L * 4) = v;
        float ls = (v.x + v.y) + (v.z + v.w);
        float lq = (v.x * v.x + v.y * v.y) + (v.z * v.z + v.w * v.w);
#pragma unroll
        for (int o = 16; o > 0; o >>= 1) {
            ls += __shfl_xor_sync(0xFFFFFFFFu, ls, o);
            lq += __shfl_xor_sync(0xFFFFFFFFu, lq, o);
        }
        if (L == 0) {
            g_ps[(size_t)blk2 * Cq + jg] = ls;
            g_pq[(size_t)blk2 * Cq + jg] = lq;
        }
    }
}

// ============================================================
// stats: single-block deterministic multiplicity-weighted reduction
// ============================================================
__global__ __launch_bounds__(1024) void stats_kernel(const float* __restrict__ gamma,
                                                     const float* __restrict__ beta) {
    __shared__ float ss[8][Cq], sq[8][Cq];
    const int j = threadIdx.x & 127;
    const int g = threadIdx.x >> 7;   // 0..7
    float s = 0.f, q = 0.f;
    for (int r = g; r < NBLK2; r += 8) {
        float w = (float)g_cnt[r >> 5];
        s += w * g_ps[(size_t)r * Cq + j];
        q += w * g_pq[(size_t)r * Cq + j];
    }
    ss[g][j] = s;
    sq[g][j] = q;
    __syncthreads();
    if (g == 0) {
        float S = 0.f, Q = 0.f;
#pragma unroll
        for (int i = 0; i < 8; i++) { S += ss[i][j]; Q += sq[i][j]; }
        const float inv = 1.0f / (float)(Bq * Pq);
        float mean = S * inv;
        float var = Q * inv - mean * mean;
        float sc = rsqrtf(var + EPSq) * gamma[j];
        g_scale[j] = sc;
        g_shift[j] = beta[j] - mean * sc;
    }
}

// ============================================================
// out: scale+shift+relu, pure coalesced copy (Y already [s][j][p])
// ============================================================
__global__ __launch_bounds__(256) void out_kernel(float* __restrict__ out,
                                                  const int* __restrict__ didx) {
    const int b = blockIdx.x >> 7;
    const int j = blockIdx.x & 127;
    const int src = didx[b];
    const float sc = g_scale[j];
    const float sh = g_shift[j];
    const float4* in = reinterpret_cast<const float4*>(
        g_Yt + ((size_t)src * Cq + j) * Pq);
    float4* op = reinterpret_cast<float4*>(out + (size_t)blockIdx.x * Pq);
#pragma unroll
    for (int k = 0; k < 4; k++) {
        int idx = threadIdx.x + k * 256;
        float4 v = in[idx];
        v.x = fmaxf(fmaf(v.x, sc, sh), 0.f);
        v.y = fmaxf(fmaf(v.y, sc, sh), 0.f);
        v.z = fmaxf(fmaf(v.z, sc, sh), 0.f);
        v.w = fmaxf(fmaf(v.w, sc, sh), 0.f);
        op[idx] = v;
    }
}

// ============================================================
// Launch
// ============================================================
extern "C" void kernel_launch(void* const* d_in, const int* in_sizes, int n_in,
                              void* d_out, int out_size) {
    const float* xyz    = (const float*)d_in[0];
    const float* points = (const float*)d_in[1];
    const float* lc     = (const float*)d_in[2];
    const int*   nbr    = (const int*)d_in[3];
    const int*   didx   = (const int*)d_in[4];
    const float* Ww     = (const float*)d_in[5];
    const float* bw     = (const float*)d_in[6];
    const float* Wl     = (const float*)d_in[7];
    const float* bl     = (const float*)d_in[8];
    const float* gamma  = (const float*)d_in[9];
    const float* beta   = (const float*)d_in[10];
    float* out = (float*)d_out;

    cudaMemcpyAsync(out, xyz, (size_t)Bq * Pq * 3 * sizeof(float),
                    cudaMemcpyDeviceToDevice, 0);

    cudaFuncSetAttribute(gemm_kernel,
                         cudaFuncAttributeMaxDynamicSharedMemorySize, GSM_TOTAL);

    prep_kernel<<<256, 256>>>(Ww, bw, Wl, didx);
    convert_kernel<<<(Bq * Nq * Cq) / 1024, 256>>>(points);

    dim3 gg(GBLK_PER_B, Bq);
    gather_kernel<<<gg, 128>>>(lc, nbr);

    dim3 g2(NPTILE * 2, Bq);
    gemm_kernel<<<g2, 256, GSM_TOTAL>>>(bl);

    stats_kernel<<<1, 1024>>>(gamma, beta);

    out_kernel<<<Bq * Cq, 256>>>(out + (size_t)Bq * Pq * 3, didx);
}

// round 8
// speedup vs baseline: 4.7957x; 1.1130x over previous
#include <cuda_runtime.h>
#include <cuda_bf16.h>
#include <cuda_fp16.h>
#include <cstdint>
#include <cstddef>

// Problem constants
#define Bq 8
#define Nq 4096
#define Pq 4096
#define Kq 32
#define Cq 128
#define Wq 16
#define EPSq 1e-5f

#define TPT 16                        // points per gather block
#define GBLK_PER_B (Pq / TPT)         // 256
#define NPTILE (Pq / 128)             // 32 p-tiles per batch
#define NBLK2 (Bq * NPTILE)           // 256 stat rows

// ------------------- device globals (no allocation allowed) -------------------
__device__ __align__(256) __half g_Ph[(size_t)Bq * Nq * Cq];     // fp16 points
__device__ __align__(256) __half g_S[(size_t)Bq * Pq * 512];     // fp16 S, [s][p][i]
__device__ __align__(256) __half g_Ahf[128 * 512];               // A' fp16, [j][i]
__device__ float g_Yt[(size_t)Bq * Cq * Pq];                     // [s][j][p]
__device__ float g_ps[NBLK2 * Cq];
__device__ float g_pq[NBLK2 * Cq];
__device__ float g_scale[Cq];
__device__ float g_shift[Cq];
__device__ int   g_cnt[Bq];

// ------------------- helpers -------------------
__device__ __forceinline__ unsigned long long pk2(float x, float y) {
    unsigned long long r;
    asm("mov.b64 %0, {%1,%2};" : "=l"(r) : "f"(x), "f"(y));
    return r;
}
__device__ __forceinline__ void fma2(unsigned long long& d,
                                     unsigned long long a,
                                     unsigned long long b) {
    asm("fma.rn.f32x2 %0, %1, %2, %0;" : "+l"(d) : "l"(a), "l"(b));
}
__device__ __forceinline__ float2 up2(unsigned long long v) {
    float x, y;
    asm("mov.b64 {%0,%1}, %2;" : "=f"(x), "=f"(y) : "l"(v));
    return make_float2(x, y);
}
__device__ __forceinline__ uint32_t smem_to_u32(const void* p) {
    uint32_t a;
    asm("{ .reg .u64 t; cvta.to.shared.u64 t, %1; cvt.u32.u64 %0, t; }"
        : "=r"(a) : "l"(p));
    return a;
}

#define CP_ASYNC16(dst, src) \
    asm volatile("cp.async.cg.shared.global [%0], [%1], 16;" \
                 :: "r"(dst), "l"(src) : "memory")
#define CP_COMMIT() asm volatile("cp.async.commit_group;" ::: "memory")
#define CP_WAIT(n)  asm volatile("cp.async.wait_group %0;" :: "n"(n) : "memory")

__device__ __forceinline__ void ldsm_x4(uint32_t addr, uint32_t* r) {
    asm volatile("ldmatrix.sync.aligned.m8n8.x4.shared.b16 {%0,%1,%2,%3}, [%4];"
                 : "=r"(r[0]), "=r"(r[1]), "=r"(r[2]), "=r"(r[3]) : "r"(addr));
}
__device__ __forceinline__ void mma_f16(float* c, const uint32_t* a,
                                        uint32_t b0, uint32_t b1) {
    asm volatile(
        "mma.sync.aligned.m16n8k16.row.col.f32.f16.f16.f32 "
        "{%0,%1,%2,%3}, {%4,%5,%6,%7}, {%8,%9}, {%0,%1,%2,%3};"
        : "+f"(c[0]), "+f"(c[1]), "+f"(c[2]), "+f"(c[3])
        : "r"(a[0]), "r"(a[1]), "r"(a[2]), "r"(a[3]), "r"(b0), "r"(b1));
}

// ============================================================
// prep: A'[i=d*128+c][j] -> fp16, transposed to [j][i]; batch counts
// ============================================================
__global__ void prep_kernel(const float* __restrict__ Ww,
                            const float* __restrict__ bw,
                            const float* __restrict__ Wl,
                            const int* __restrict__ didx) {
    int idx = blockIdx.x * blockDim.x + threadIdx.x;
    if (blockIdx.x == 0 && threadIdx.x < Bq) {
        int c = 0;
#pragma unroll
        for (int b = 0; b < Bq; b++) c += (didx[b] == (int)threadIdx.x);
        g_cnt[threadIdx.x] = c;
    }
    if (idx >= 4 * Cq * Cq) return;
    int d = idx >> 14;
    int c = (idx >> 7) & (Cq - 1);
    int j = idx & (Cq - 1);
    float acc = 0.f;
#pragma unroll
    for (int w = 0; w < Wq; w++) {
        float coef = (d < 3) ? Ww[d * Wq + w] : bw[w];
        acc = fmaf(coef, Wl[(c * Wq + w) * Cq + j], acc);
    }
    int i = (d << 7) | c;
    g_Ahf[(size_t)j * 512 + i] = __float2half_rn(acc);
}

// ============================================================
// convert: points fp32 -> fp16
// ============================================================
__global__ __launch_bounds__(256) void convert_kernel(const float* __restrict__ points) {
    size_t idx = ((size_t)blockIdx.x * 256 + threadIdx.x) * 4;
    float4 v = *reinterpret_cast<const float4*>(points + idx);
    *reinterpret_cast<__half2*>(g_Ph + idx) = __floats2half2_rn(v.x, v.y);
    *reinterpret_cast<__half2*>(g_Ph + idx + 2) = __floats2half2_rn(v.z, v.w);
}

// ============================================================
// gather: S[p,i] = sum_k coef[k,d] * points_h[s, nbr[k], c]; emit fp16
// ============================================================
__global__ __launch_bounds__(128, 8) void gather_kernel(
    const float* __restrict__ lc,
    const int* __restrict__ nbr) {
    __shared__ ulonglong2 s_L[TPT][Kq];
    __shared__ uint32_t s_off[TPT][Kq];

    const int tid = threadIdx.x;
    const int s = blockIdx.y;
    if (g_cnt[s] == 0) return;
    const int p0 = blockIdx.x * TPT;
    const size_t base = ((size_t)s * Pq + p0) * Kq;

    for (int i = tid; i < TPT * Kq; i += 128) {
        int t = i >> 5, k = i & 31;
        s_off[t][k] = (uint32_t)nbr[base + (size_t)t * Kq + k] << 8;   // *256B row
        const float* Lp = lc + (base + (size_t)t * Kq + k) * 3;
        s_L[t][k] = make_ulonglong2(pk2(Lp[0], Lp[1]), pk2(Lp[2], 1.0f));
    }
    __syncthreads();

    const int h = tid >> 6, c2 = tid & 63;
    const char* ptsb = (const char*)(g_Ph + (size_t)s * Nq * Cq) + 4 * c2;

#pragma unroll 1
    for (int t8 = 0; t8 < 8; t8++) {
        const int t = t8 * 2 + h;
        unsigned long long e01 = 0ull, e23 = 0ull, o01 = 0ull, o23 = 0ull;
#pragma unroll
        for (int k = 0; k < Kq; k++) {
            __half2 hv = *reinterpret_cast<const __half2*>(ptsb + s_off[t][k]);
            float2 v = __half22float2(hv);
            ulonglong2 L = s_L[t][k];
            unsigned long long vx = pk2(v.x, v.x), vy = pk2(v.y, v.y);
            fma2(e01, vx, L.x);
            fma2(e23, vx, L.y);
            fma2(o01, vy, L.x);
            fma2(o23, vy, L.y);
        }
        float2 fe01 = up2(e01), fe23 = up2(e23);
        float2 fo01 = up2(o01), fo23 = up2(o23);
        const size_t rb = ((size_t)s * Pq + p0 + t) * 512;
        float ev[4] = {fe01.x, fe01.y, fe23.x, fe23.y};
        float ov[4] = {fo01.x, fo01.y, fo23.x, fo23.y};
#pragma unroll
        for (int d = 0; d < 4; d++) {
            *reinterpret_cast<__half2*>(g_S + rb + d * 128 + 2 * c2) =
                __floats2half2_rn(ev[d], ov[d]);
        }
    }
}

// ============================================================
// GEMM: Y[p,j] = S[p,i] * A'[j,i]^T  via mma.sync fp16 (single product)
//   block tile: 128p x 64j, K chunks of 32; grid 512
//   smem rows: 32 fp16 = 64B data padded to 80B (conflict-free ldmatrix)
// ============================================================
#define STILE_B 10240                // 128 rows * 80B
#define ATILE_B 5120                 // 64 rows * 80B
#define OFF_S   0
#define OFF_A   (STILE_B)
#define BUF_B   (STILE_B + ATILE_B)       // 15360
#define GSM_TOTAL 33792                   // max(2*BUF_B=30720, epilogue 64*132*4)

__global__ __launch_bounds__(256, 3) void gemm_kernel(const float* __restrict__ bl) {
    extern __shared__ __align__(128) char sm[];
    const int tid = threadIdx.x;
    const int wid = tid >> 5;
    const int L = tid & 31;
    const int srcb = blockIdx.y;
    if (g_cnt[srcb] == 0) return;
    const int pt = blockIdx.x >> 1;
    const int jh = blockIdx.x & 1;     // which 64-j half
    const int wm = wid >> 1;           // 0..3  (p dim, 32 each)
    const int wn = wid & 1;            // 0..1  (j dim, 32 each)

    const uint32_t smb = smem_to_u32(sm);
    const __half* Sp = g_S + ((size_t)srcb * Pq + pt * 128) * 512;
    const __half* Ah = g_Ahf + (size_t)(jh * 64) * 512;

    const int r0c = tid >> 2, seg0 = tid & 3;    // copy mapping

    float acc[2][4][4];
#pragma unroll
    for (int mt = 0; mt < 2; mt++)
#pragma unroll
        for (int nt = 0; nt < 4; nt++)
#pragma unroll
            for (int q = 0; q < 4; q++) acc[mt][nt][q] = 0.f;

    const int grp = L >> 3, lr = L & 7;
    const uint32_t aRow = (uint32_t)(wm * 32 + (grp & 1) * 8 + lr) * 80
                        + (uint32_t)(grp >> 1) * 16;
    const uint32_t bRow = (uint32_t)(wn * 32 + (grp >> 1) * 8 + lr) * 80
                        + (uint32_t)(grp & 1) * 16;

#define ISSUE(kc, buf) do {                                                     \
        uint32_t bb = smb + (buf) * BUF_B;                                      \
        size_t ko = (size_t)(kc) * 32 + seg0 * 8;                               \
        uint32_t dsto = (uint32_t)r0c * 80 + (uint32_t)seg0 * 16;               \
        CP_ASYNC16(bb + OFF_S + dsto, (const char*)(Sp + (size_t)r0c * 512 + ko)); \
        CP_ASYNC16(bb + OFF_S + dsto + 64 * 80,                                 \
                   (const char*)(Sp + (size_t)(r0c + 64) * 512 + ko));          \
        CP_ASYNC16(bb + OFF_A + dsto, (const char*)(Ah + (size_t)r0c * 512 + ko)); \
        CP_COMMIT();                                                            \
    } while (0)

    ISSUE(0, 0);

#pragma unroll 1
    for (int kc = 0; kc < 16; kc++) {
        if (kc < 15) { ISSUE(kc + 1, (kc + 1) & 1); CP_WAIT(1); }
        else         { CP_WAIT(0); }
        __syncthreads();

        const uint32_t bb = smb + (kc & 1) * BUF_B;
#pragma unroll
        for (int ks = 0; ks < 2; ks++) {
            uint32_t af[2][4];
#pragma unroll
            for (int mt = 0; mt < 2; mt++) {
                uint32_t ao = aRow + (uint32_t)mt * (16 * 80) + (uint32_t)ks * 32;
                ldsm_x4(bb + OFF_S + ao, af[mt]);
            }
#pragma unroll
            for (int ng = 0; ng < 2; ng++) {
                uint32_t bh[4];
                uint32_t bo = bRow + (uint32_t)ng * (16 * 80) + (uint32_t)ks * 32;
                ldsm_x4(bb + OFF_A + bo, bh);
#pragma unroll
                for (int mt = 0; mt < 2; mt++) {
#pragma unroll
                    for (int t2 = 0; t2 < 2; t2++) {
                        mma_f16(acc[mt][2 * ng + t2], af[mt],
                                bh[2 * t2], bh[2 * t2 + 1]);
                    }
                }
            }
        }
        __syncthreads();
    }

    // ---- epilogue: C frags -> smem [64j][132] -> coalesced Y + LN partials ----
    float* yt = (float*)sm;
    {
        const int pb = wm * 32 + (L >> 2);
        const int jb = wn * 32 + ((L & 3) << 1);
#pragma unroll
        for (int mt = 0; mt < 2; mt++) {
#pragma unroll
            for (int nt = 0; nt < 4; nt++) {
                const float* c = acc[mt][nt];
                int p = pb + mt * 16;
                int j = jb + nt * 8;
                yt[j * 132 + p] = c[0];
                yt[(j + 1) * 132 + p] = c[1];
                yt[j * 132 + p + 8] = c[2];
                yt[(j + 1) * 132 + p + 8] = c[3];
            }
        }
    }
    __syncthreads();

    const int blk2 = srcb * NPTILE + pt;
#pragma unroll 1
    for (int rr = 0; rr < 8; rr++) {
        int j = wid * 8 + rr;          // local j in [0,64)
        int jg = jh * 64 + j;          // global output channel
        float blj = __ldg(bl + jg);
        float4 v = *reinterpret_cast<const float4*>(yt + j * 132 + L * 4);
        v.x += blj; v.y += blj; v.z += blj; v.w += blj;
        *reinterpret_cast<float4*>(
            g_Yt + ((size_t)srcb * Cq + jg) * Pq + pt * 128 + L * 4) = v;
        float ls = (v.x + v.y) + (v.z + v.w);
        float lq = (v.x * v.x + v.y * v.y) + (v.z * v.z + v.w * v.w);
#pragma unroll
        for (int o = 16; o > 0; o >>= 1) {
            ls += __shfl_xor_sync(0xFFFFFFFFu, ls, o);
            lq += __shfl_xor_sync(0xFFFFFFFFu, lq, o);
        }
        if (L == 0) {
            g_ps[(size_t)blk2 * Cq + jg] = ls;
            g_pq[(size_t)blk2 * Cq + jg] = lq;
        }
    }
}

// ============================================================
// stats: single-block deterministic multiplicity-weighted reduction
// ============================================================
__global__ __launch_bounds__(1024) void stats_kernel(const float* __restrict__ gamma,
                                                     const float* __restrict__ beta) {
    __shared__ float ss[8][Cq], sq[8][Cq];
    const int j = threadIdx.x & 127;
    const int g = threadIdx.x >> 7;   // 0..7
    float s = 0.f, q = 0.f;
    for (int r = g; r < NBLK2; r += 8) {
        float w = (float)g_cnt[r >> 5];
        s += w * g_ps[(size_t)r * Cq + j];
        q += w * g_pq[(size_t)r * Cq + j];
    }
    ss[g][j] = s;
    sq[g][j] = q;
    __syncthreads();
    if (g == 0) {
        float S = 0.f, Q = 0.f;
#pragma unroll
        for (int i = 0; i < 8; i++) { S += ss[i][j]; Q += sq[i][j]; }
        const float inv = 1.0f / (float)(Bq * Pq);
        float mean = S * inv;
        float var = Q * inv - mean * mean;
        float sc = rsqrtf(var + EPSq) * gamma[j];
        g_scale[j] = sc;
        g_shift[j] = beta[j] - mean * sc;
    }
}

// ============================================================
// out: scale+shift+relu, pure coalesced copy (Y already [s][j][p])
// ============================================================
__global__ __launch_bounds__(256) void out_kernel(float* __restrict__ out,
                                                  const int* __restrict__ didx) {
    const int b = blockIdx.x >> 7;
    const int j = blockIdx.x & 127;
    const int src = didx[b];
    const float sc = g_scale[j];
    const float sh = g_shift[j];
    const float4* in = reinterpret_cast<const float4*>(
        g_Yt + ((size_t)src * Cq + j) * Pq);
    float4* op = reinterpret_cast<float4*>(out + (size_t)blockIdx.x * Pq);
#pragma unroll
    for (int k = 0; k < 4; k++) {
        int idx = threadIdx.x + k * 256;
        float4 v = in[idx];
        v.x = fmaxf(fmaf(v.x, sc, sh), 0.f);
        v.y = fmaxf(fmaf(v.y, sc, sh), 0.f);
        v.z = fmaxf(fmaf(v.z, sc, sh), 0.f);
        v.w = fmaxf(fmaf(v.w, sc, sh), 0.f);
        op[idx] = v;
    }
}

// ============================================================
// Launch
// ============================================================
extern "C" void kernel_launch(void* const* d_in, const int* in_sizes, int n_in,
                              void* d_out, int out_size) {
    const float* xyz    = (const float*)d_in[0];
    const float* points = (const float*)d_in[1];
    const float* lc     = (const float*)d_in[2];
    const int*   nbr    = (const int*)d_in[3];
    const int*   didx   = (const int*)d_in[4];
    const float* Ww     = (const float*)d_in[5];
    const float* bw     = (const float*)d_in[6];
    const float* Wl     = (const float*)d_in[7];
    const float* bl     = (const float*)d_in[8];
    const float* gamma  = (const float*)d_in[9];
    const float* beta   = (const float*)d_in[10];
    float* out = (float*)d_out;

    cudaMemcpyAsync(out, xyz, (size_t)Bq * Pq * 3 * sizeof(float),
                    cudaMemcpyDeviceToDevice, 0);

    cudaFuncSetAttribute(gemm_kernel,
                         cudaFuncAttributeMaxDynamicSharedMemorySize, GSM_TOTAL);

    prep_kernel<<<256, 256>>>(Ww, bw, Wl, didx);
    convert_kernel<<<(Bq * Nq * Cq) / 1024, 256>>>(points);

    dim3 gg(GBLK_PER_B, Bq);
    gather_kernel<<<gg, 128>>>(lc, nbr);

    dim3 g2(NPTILE * 2, Bq);
    gemm_kernel<<<g2, 256, GSM_TOTAL>>>(bl);

    stats_kernel<<<1, 1024>>>(gamma, beta);

    out_kernel<<<Bq * Cq, 256>>>(out + (size_t)Bq * Pq * 3, didx);
}

// round 9
// speedup vs baseline: 4.9697x; 1.0363x over previous
#include <cuda_runtime.h>
#include <cuda_bf16.h>
#include <cuda_fp16.h>
#include <cstdint>
#include <cstddef>

// Problem constants
#define Bq 8
#define Nq 4096
#define Pq 4096
#define Kq 32
#define Cq 128
#define Wq 16
#define EPSq 1e-5f

#define TPT 16                        // points per gather block
#define GBLK_PER_B (Pq / TPT)         // 256
#define NPTILE (Pq / 128)             // 32 p-tiles per batch
#define NBLK2 (Bq * NPTILE)           // 256 stat rows

// ------------------- device globals (no allocation allowed) -------------------
__device__ __align__(256) __half g_Ph[(size_t)Bq * Nq * Cq];     // fp16 points
__device__ __align__(256) __half g_S[(size_t)Bq * Pq * 512];     // fp16 S, [s][p][i]
__device__ __align__(256) __half g_Ahf[128 * 512];               // A' fp16, [j][i]
__device__ __align__(256) __half g_Yth[(size_t)Bq * Cq * Pq];    // fp16 Y, [s][j][p]
__device__ float g_ps[NBLK2 * Cq];
__device__ float g_pq[NBLK2 * Cq];
__device__ float g_scale[Cq];
__device__ float g_shift[Cq];
__device__ int   g_cnt[Bq];

// ------------------- helpers -------------------
__device__ __forceinline__ unsigned long long pk2(float x, float y) {
    unsigned long long r;
    asm("mov.b64 %0, {%1,%2};" : "=l"(r) : "f"(x), "f"(y));
    return r;
}
__device__ __forceinline__ void fma2(unsigned long long& d,
                                     unsigned long long a,
                                     unsigned long long b) {
    asm("fma.rn.f32x2 %0, %1, %2, %0;" : "+l"(d) : "l"(a), "l"(b));
}
__device__ __forceinline__ float2 up2(unsigned long long v) {
    float x, y;
    asm("mov.b64 {%0,%1}, %2;" : "=f"(x), "=f"(y) : "l"(v));
    return make_float2(x, y);
}
__device__ __forceinline__ uint32_t smem_to_u32(const void* p) {
    uint32_t a;
    asm("{ .reg .u64 t; cvta.to.shared.u64 t, %1; cvt.u32.u64 %0, t; }"
        : "=r"(a) : "l"(p));
    return a;
}
__device__ __forceinline__ __half2 h2_from_u32(uint32_t u) {
    __half2 h;
    *reinterpret_cast<uint32_t*>(&h) = u;
    return h;
}

#define CP_ASYNC16(dst, src) \
    asm volatile("cp.async.cg.shared.global [%0], [%1], 16;" \
                 :: "r"(dst), "l"(src) : "memory")
#define CP_COMMIT() asm volatile("cp.async.commit_group;" ::: "memory")
#define CP_WAIT(n)  asm volatile("cp.async.wait_group %0;" :: "n"(n) : "memory")

__device__ __forceinline__ void ldsm_x4(uint32_t addr, uint32_t* r) {
    asm volatile("ldmatrix.sync.aligned.m8n8.x4.shared.b16 {%0,%1,%2,%3}, [%4];"
                 : "=r"(r[0]), "=r"(r[1]), "=r"(r[2]), "=r"(r[3]) : "r"(addr));
}
__device__ __forceinline__ void mma_f16(float* c, const uint32_t* a,
                                        uint32_t b0, uint32_t b1) {
    asm volatile(
        "mma.sync.aligned.m16n8k16.row.col.f32.f16.f16.f32 "
        "{%0,%1,%2,%3}, {%4,%5,%6,%7}, {%8,%9}, {%0,%1,%2,%3};"
        : "+f"(c[0]), "+f"(c[1]), "+f"(c[2]), "+f"(c[3])
        : "r"(a[0]), "r"(a[1]), "r"(a[2]), "r"(a[3]), "r"(b0), "r"(b1));
}

// ============================================================
// prep: A'[i=d*128+c][j] -> fp16, transposed to [j][i]; batch counts
// ============================================================
__global__ void prep_kernel(const float* __restrict__ Ww,
                            const float* __restrict__ bw,
                            const float* __restrict__ Wl,
                            const int* __restrict__ didx) {
    int idx = blockIdx.x * blockDim.x + threadIdx.x;
    if (blockIdx.x == 0 && threadIdx.x < Bq) {
        int c = 0;
#pragma unroll
        for (int b = 0; b < Bq; b++) c += (didx[b] == (int)threadIdx.x);
        g_cnt[threadIdx.x] = c;
    }
    if (idx >= 4 * Cq * Cq) return;
    int d = idx >> 14;
    int c = (idx >> 7) & (Cq - 1);
    int j = idx & (Cq - 1);
    float acc = 0.f;
#pragma unroll
    for (int w = 0; w < Wq; w++) {
        float coef = (d < 3) ? Ww[d * Wq + w] : bw[w];
        acc = fmaf(coef, Wl[(c * Wq + w) * Cq + j], acc);
    }
    int i = (d << 7) | c;
    g_Ahf[(size_t)j * 512 + i] = __float2half_rn(acc);
}

// ============================================================
// convert: points fp32 -> fp16
// ============================================================
__global__ __launch_bounds__(256) void convert_kernel(const float* __restrict__ points) {
    size_t idx = ((size_t)blockIdx.x * 256 + threadIdx.x) * 4;
    float4 v = *reinterpret_cast<const float4*>(points + idx);
    *reinterpret_cast<__half2*>(g_Ph + idx) = __floats2half2_rn(v.x, v.y);
    *reinterpret_cast<__half2*>(g_Ph + idx + 2) = __floats2half2_rn(v.z, v.w);
}

// ============================================================
// gather: S[p,i] = sum_k coef[k,d] * points_h[s, nbr[k], c]; emit fp16
//   thread handles 4 channels (c4) x 4 points via LDG.64
// ============================================================
__global__ __launch_bounds__(128, 8) void gather_kernel(
    const float* __restrict__ lc,
    const int* __restrict__ nbr) {
    __shared__ ulonglong2 s_L[TPT][Kq];
    __shared__ uint32_t s_off[TPT][Kq];

    const int tid = threadIdx.x;
    const int s = blockIdx.y;
    if (g_cnt[s] == 0) return;
    const int p0 = blockIdx.x * TPT;
    const size_t base = ((size_t)s * Pq + p0) * Kq;

    for (int i = tid; i < TPT * Kq; i += 128) {
        int t = i >> 5, k = i & 31;
        s_off[t][k] = (uint32_t)nbr[base + (size_t)t * Kq + k] << 8;   // *256B row
        const float* Lp = lc + (base + (size_t)t * Kq + k) * 3;
        s_L[t][k] = make_ulonglong2(pk2(Lp[0], Lp[1]), pk2(Lp[2], 1.0f));
    }
    __syncthreads();

    const int c4 = tid & 31;          // channel quad: channels 4*c4 .. 4*c4+3
    const int h = tid >> 5;           // 0..3 point group
    const char* ptsb = (const char*)(g_Ph + (size_t)s * Nq * Cq) + 8 * c4;

#pragma unroll 1
    for (int tt = 0; tt < 4; tt++) {
        const int t = tt * 4 + h;
        unsigned long long a01[4], a23[4];
#pragma unroll
        for (int c = 0; c < 4; c++) { a01[c] = 0ull; a23[c] = 0ull; }
#pragma unroll
        for (int k = 0; k < Kq; k++) {
            uint2 w = *reinterpret_cast<const uint2*>(ptsb + s_off[t][k]);
            float2 v0 = __half22float2(h2_from_u32(w.x));
            float2 v1 = __half22float2(h2_from_u32(w.y));
            ulonglong2 L = s_L[t][k];
            unsigned long long p0v = pk2(v0.x, v0.x), p1v = pk2(v0.y, v0.y);
            unsigned long long p2v = pk2(v1.x, v1.x), p3v = pk2(v1.y, v1.y);
            fma2(a01[0], p0v, L.x); fma2(a23[0], p0v, L.y);
            fma2(a01[1], p1v, L.x); fma2(a23[1], p1v, L.y);
            fma2(a01[2], p2v, L.x); fma2(a23[2], p2v, L.y);
            fma2(a01[3], p3v, L.x); fma2(a23[3], p3v, L.y);
        }
        const size_t rb = ((size_t)s * Pq + p0 + t) * 512;
        float2 f01[4], f23[4];
#pragma unroll
        for (int c = 0; c < 4; c++) { f01[c] = up2(a01[c]); f23[c] = up2(a23[c]); }
        // d=0: f01[c].x ; d=1: f01[c].y ; d=2: f23[c].x ; d=3: f23[c].y
        uint2 st;
        __half2 ha, hb;
        ha = __floats2half2_rn(f01[0].x, f01[1].x);
        hb = __floats2half2_rn(f01[2].x, f01[3].x);
        st.x = *reinterpret_cast<uint32_t*>(&ha);
        st.y = *reinterpret_cast<uint32_t*>(&hb);
        *reinterpret_cast<uint2*>(g_S + rb + 0 * 128 + 4 * c4) = st;
        ha = __floats2half2_rn(f01[0].y, f01[1].y);
        hb = __floats2half2_rn(f01[2].y, f01[3].y);
        st.x = *reinterpret_cast<uint32_t*>(&ha);
        st.y = *reinterpret_cast<uint32_t*>(&hb);
        *reinterpret_cast<uint2*>(g_S + rb + 1 * 128 + 4 * c4) = st;
        ha = __floats2half2_rn(f23[0].x, f23[1].x);
        hb = __floats2half2_rn(f23[2].x, f23[3].x);
        st.x = *reinterpret_cast<uint32_t*>(&ha);
        st.y = *reinterpret_cast<uint32_t*>(&hb);
        *reinterpret_cast<uint2*>(g_S + rb + 2 * 128 + 4 * c4) = st;
        ha = __floats2half2_rn(f23[0].y, f23[1].y);
        hb = __floats2half2_rn(f23[2].y, f23[3].y);
        st.x = *reinterpret_cast<uint32_t*>(&ha);
        st.y = *reinterpret_cast<uint32_t*>(&hb);
        *reinterpret_cast<uint2*>(g_S + rb + 3 * 128 + 4 * c4) = st;
    }
}

// ============================================================
// GEMM: Y[p,j] = S[p,i] * A'[j,i]^T  via mma.sync fp16, 3-stage pipeline
//   block tile: 128p x 64j, K chunks of 32; grid 512; ONE barrier/chunk
// ============================================================
#define STILE_B 10240                // 128 rows * 80B
#define ATILE_B 5120                 // 64 rows * 80B
#define OFF_S   0
#define OFF_A   (STILE_B)
#define BUF_B   (STILE_B + ATILE_B)       // 15360
#define NSTAGE  3
#define GSM_TOTAL (NSTAGE * BUF_B)        // 46080 (epilogue 64*132*4=33792 fits)

__global__ __launch_bounds__(256, 3) void gemm_kernel(const float* __restrict__ bl) {
    extern __shared__ __align__(128) char sm[];
    const int tid = threadIdx.x;
    const int wid = tid >> 5;
    const int L = tid & 31;
    const int srcb = blockIdx.y;
    if (g_cnt[srcb] == 0) return;
    const int pt = blockIdx.x >> 1;
    const int jh = blockIdx.x & 1;     // which 64-j half
    const int wm = wid >> 1;           // 0..3  (p dim, 32 each)
    const int wn = wid & 1;            // 0..1  (j dim, 32 each)

    const uint32_t smb = smem_to_u32(sm);
    const __half* Sp = g_S + ((size_t)srcb * Pq + pt * 128) * 512;
    const __half* Ah = g_Ahf + (size_t)(jh * 64) * 512;

    const int r0c = tid >> 2, seg0 = tid & 3;    // copy mapping

    float acc[2][4][4];
#pragma unroll
    for (int mt = 0; mt < 2; mt++)
#pragma unroll
        for (int nt = 0; nt < 4; nt++)
#pragma unroll
            for (int q = 0; q < 4; q++) acc[mt][nt][q] = 0.f;

    const int grp = L >> 3, lr = L & 7;
    const uint32_t aRow = (uint32_t)(wm * 32 + (grp & 1) * 8 + lr) * 80
                        + (uint32_t)(grp >> 1) * 16;
    const uint32_t bRow = (uint32_t)(wn * 32 + (grp >> 1) * 8 + lr) * 80
                        + (uint32_t)(grp & 1) * 16;

#define ISSUE(kc, buf) do {                                                     \
        uint32_t bb = smb + (uint32_t)(buf) * BUF_B;                            \
        size_t ko = (size_t)(kc) * 32 + seg0 * 8;                               \
        uint32_t dsto = (uint32_t)r0c * 80 + (uint32_t)seg0 * 16;               \
        CP_ASYNC16(bb + OFF_S + dsto, (const char*)(Sp + (size_t)r0c * 512 + ko)); \
        CP_ASYNC16(bb + OFF_S + dsto + 64 * 80,                                 \
                   (const char*)(Sp + (size_t)(r0c + 64) * 512 + ko));          \
        CP_ASYNC16(bb + OFF_A + dsto, (const char*)(Ah + (size_t)r0c * 512 + ko)); \
        CP_COMMIT();                                                            \
    } while (0)

    ISSUE(0, 0);
    ISSUE(1, 1);

    int buf = 0, nbuf = 2;   // buf: stage to compute; nbuf: stage to fill next
#pragma unroll 1
    for (int kc = 0; kc < 16; kc++) {
        if (kc == 15) { CP_WAIT(0); } else { CP_WAIT(1); }
        __syncthreads();
        if (kc < 14) {
            ISSUE(kc + 2, nbuf);
            nbuf = (nbuf == 2) ? 0 : nbuf + 1;
        }

        const uint32_t bb = smb + (uint32_t)buf * BUF_B;
        buf = (buf == 2) ? 0 : buf + 1;
#pragma unroll
        for (int ks = 0; ks < 2; ks++) {
            uint32_t af[2][4];
#pragma unroll
            for (int mt = 0; mt < 2; mt++) {
                uint32_t ao = aRow + (uint32_t)mt * (16 * 80) + (uint32_t)ks * 32;
                ldsm_x4(bb + OFF_S + ao, af[mt]);
            }
#pragma unroll
            for (int ng = 0; ng < 2; ng++) {
                uint32_t bh[4];
                uint32_t bo = bRow + (uint32_t)ng * (16 * 80) + (uint32_t)ks * 32;
                ldsm_x4(bb + OFF_A + bo, bh);
#pragma unroll
                for (int mt = 0; mt < 2; mt++) {
#pragma unroll
                    for (int t2 = 0; t2 < 2; t2++) {
                        mma_f16(acc[mt][2 * ng + t2], af[mt],
                                bh[2 * t2], bh[2 * t2 + 1]);
                    }
                }
            }
        }
    }
    __syncthreads();

    // ---- epilogue: C frags -> smem [64j][132] -> coalesced fp16 Y + LN partials ----
    float* yt = (float*)sm;
    {
        const int pb = wm * 32 + (L >> 2);
        const int jb = wn * 32 + ((L & 3) << 1);
#pragma unroll
        for (int mt = 0; mt < 2; mt++) {
#pragma unroll
            for (int nt = 0; nt < 4; nt++) {
                const float* c = acc[mt][nt];
                int p = pb + mt * 16;
                int j = jb + nt * 8;
                yt[j * 132 + p] = c[0];
                yt[(j + 1) * 132 + p] = c[1];
                yt[j * 132 + p + 8] = c[2];
                yt[(j + 1) * 132 + p + 8] = c[3];
            }
        }
    }
    __syncthreads();

    const int blk2 = srcb * NPTILE + pt;
#pragma unroll 1
    for (int rr = 0; rr < 8; rr++) {
        int j = wid * 8 + rr;          // local j in [0,64)
        int jg = jh * 64 + j;          // global output channel
        float blj = __ldg(bl + jg);
        float4 v = *reinterpret_cast<const float4*>(yt + j * 132 + L * 4);
        v.x += blj; v.y += blj; v.z += blj; v.w += blj;
        __half2 h0 = __floats2half2_rn(v.x, v.y);
        __half2 h1 = __floats2half2_rn(v.z, v.w);
        uint2 st;
        st.x = *reinterpret_cast<uint32_t*>(&h0);
        st.y = *reinterpret_cast<uint32_t*>(&h1);
        *reinterpret_cast<uint2*>(
            g_Yth + ((size_t)srcb * Cq + jg) * Pq + pt * 128 + L * 4) = st;
        float ls = (v.x + v.y) + (v.z + v.w);
        float lq = (v.x * v.x + v.y * v.y) + (v.z * v.z + v.w * v.w);
#pragma unroll
        for (int o = 16; o > 0; o >>= 1) {
            ls += __shfl_xor_sync(0xFFFFFFFFu, ls, o);
            lq += __shfl_xor_sync(0xFFFFFFFFu, lq, o);
        }
        if (L == 0) {
            g_ps[(size_t)blk2 * Cq + jg] = ls;
            g_pq[(size_t)blk2 * Cq + jg] = lq;
        }
    }
}

// ============================================================
// stats: single-block deterministic multiplicity-weighted reduction
// ============================================================
__global__ __launch_bounds__(1024) void stats_kernel(const float* __restrict__ gamma,
                                                     const float* __restrict__ beta) {
    __shared__ float ss[8][Cq], sq[8][Cq];
    const int j = threadIdx.x & 127;
    const int g = threadIdx.x >> 7;   // 0..7
    float s = 0.f, q = 0.f;
    for (int r = g; r < NBLK2; r += 8) {
        float w = (float)g_cnt[r >> 5];
        s += w * g_ps[(size_t)r * Cq + j];
        q += w * g_pq[(size_t)r * Cq + j];
    }
    ss[g][j] = s;
    sq[g][j] = q;
    __syncthreads();
    if (g == 0) {
        float S = 0.f, Q = 0.f;
#pragma unroll
        for (int i = 0; i < 8; i++) { S += ss[i][j]; Q += sq[i][j]; }
        const float inv = 1.0f / (float)(Bq * Pq);
        float mean = S * inv;
        float var = Q * inv - mean * mean;
        float sc = rsqrtf(var + EPSq) * gamma[j];
        g_scale[j] = sc;
        g_shift[j] = beta[j] - mean * sc;
    }
}

// ============================================================
// out: scale+shift+relu, coalesced fp16 read -> fp32 write
// ============================================================
__global__ __launch_bounds__(256) void out_kernel(float* __restrict__ out,
                                                  const int* __restrict__ didx) {
    const int b = blockIdx.x >> 7;
    const int j = blockIdx.x & 127;
    const int src = didx[b];
    const float sc = g_scale[j];
    const float sh = g_shift[j];
    const uint4* in = reinterpret_cast<const uint4*>(
        g_Yth + ((size_t)src * Cq + j) * Pq);
    float4* op = reinterpret_cast<float4*>(out + (size_t)blockIdx.x * Pq);
#pragma unroll
    for (int k = 0; k < 2; k++) {
        int idx = threadIdx.x + k * 256;      // 512 uint4 per row
        uint4 v = in[idx];
        float2 a0 = __half22float2(h2_from_u32(v.x));
        float2 a1 = __half22float2(h2_from_u32(v.y));
        float2 a2 = __half22float2(h2_from_u32(v.z));
        float2 a3 = __half22float2(h2_from_u32(v.w));
        float4 o0, o1;
        o0.x = fmaxf(fmaf(a0.x, sc, sh), 0.f);
        o0.y = fmaxf(fmaf(a0.y, sc, sh), 0.f);
        o0.z = fmaxf(fmaf(a1.x, sc, sh), 0.f);
        o0.w = fmaxf(fmaf(a1.y, sc, sh), 0.f);
        o1.x = fmaxf(fmaf(a2.x, sc, sh), 0.f);
        o1.y = fmaxf(fmaf(a2.y, sc, sh), 0.f);
        o1.z = fmaxf(fmaf(a3.x, sc, sh), 0.f);
        o1.w = fmaxf(fmaf(a3.y, sc, sh), 0.f);
        op[idx * 2] = o0;
        op[idx * 2 + 1] = o1;
    }
}

// ============================================================
// Launch
// ============================================================
extern "C" void kernel_launch(void* const* d_in, const int* in_sizes, int n_in,
                              void* d_out, int out_size) {
    const float* xyz    = (const float*)d_in[0];
    const float* points = (const float*)d_in[1];
    const float* lc     = (const float*)d_in[2];
    const int*   nbr    = (const int*)d_in[3];
    const int*   didx   = (const int*)d_in[4];
    const float* Ww     = (const float*)d_in[5];
    const float* bw     = (const float*)d_in[6];
    const float* Wl     = (const float*)d_in[7];
    const float* bl     = (const float*)d_in[8];
    const float* gamma  = (const float*)d_in[9];
    const float* beta   = (const float*)d_in[10];
    float* out = (float*)d_out;

    cudaMemcpyAsync(out, xyz, (size_t)Bq * Pq * 3 * sizeof(float),
                    cudaMemcpyDeviceToDevice, 0);

    cudaFuncSetAttribute(gemm_kernel,
                         cudaFuncAttributeMaxDynamicSharedMemorySize, GSM_TOTAL);

    prep_kernel<<<256, 256>>>(Ww, bw, Wl, didx);
    convert_kernel<<<(Bq * Nq * Cq) / 1024, 256>>>(points);

    dim3 gg(GBLK_PER_B, Bq);
    gather_kernel<<<gg, 128>>>(lc, nbr);

    dim3 g2(NPTILE * 2, Bq);
    gemm_kernel<<<g2, 256, GSM_TOTAL>>>(bl);

    stats_kernel<<<1, 1024>>>(gamma, beta);

    out_kernel<<<Bq * Cq, 256>>>(out + (size_t)Bq * Pq * 3, didx);
}

// round 11
// speedup vs baseline: 5.2443x; 1.0553x over previous
#include <cuda_runtime.h>
#include <cuda_bf16.h>
#include <cuda_fp16.h>
#include <cstdint>
#include <cstddef>

// Problem constants
#define Bq 8
#define Nq 4096
#define Pq 4096
#define Kq 32
#define Cq 128
#define Wq 16
#define EPSq 1e-5f

#define TPT 16                        // points per gather block
#define GBLK_PER_B (Pq / TPT)         // 256
#define NPTILE (Pq / 128)             // 32 p-tiles per batch
#define NBLK2 (Bq * NPTILE)           // 256 stat rows

// ------------------- device globals (no allocation allowed) -------------------
__device__ __align__(256) __half g_Ph[(size_t)Bq * Nq * Cq];     // fp16 points
__device__ __align__(256) __half g_S[(size_t)Bq * Pq * 512];     // fp16 S, [s][p][i]
__device__ __align__(256) __half g_Ahf[128 * 512];               // A' fp16, [j][i]
__device__ __align__(256) __half g_Yth[(size_t)Bq * Cq * Pq];    // fp16 Y, [s][j][p]
__device__ float g_ps[NBLK2 * Cq];
__device__ float g_pq[NBLK2 * Cq];
__device__ float g_scale[Cq];
__device__ float g_shift[Cq];
__device__ int   g_cnt[Bq];

// ------------------- helpers -------------------
__device__ __forceinline__ unsigned long long pk2(float x, float y) {
    unsigned long long r;
    asm("mov.b64 %0, {%1,%2};" : "=l"(r) : "f"(x), "f"(y));
    return r;
}
__device__ __forceinline__ void fma2(unsigned long long& d,
                                     unsigned long long a,
                                     unsigned long long b) {
    asm("fma.rn.f32x2 %0, %1, %2, %0;" : "+l"(d) : "l"(a), "l"(b));
}
__device__ __forceinline__ float2 up2(unsigned long long v) {
    float x, y;
    asm("mov.b64 {%0,%1}, %2;" : "=f"(x), "=f"(y) : "l"(v));
    return make_float2(x, y);
}
__device__ __forceinline__ uint32_t smem_to_u32(const void* p) {
    uint32_t a;
    asm("{ .reg .u64 t; cvta.to.shared.u64 t, %1; cvt.u32.u64 %0, t; }"
        : "=r"(a) : "l"(p));
    return a;
}
__device__ __forceinline__ __half2 h2_from_u32(uint32_t u) {
    __half2 h;
    *reinterpret_cast<uint32_t*>(&h) = u;
    return h;
}

#define CP_ASYNC16(dst, src) \
    asm volatile("cp.async.cg.shared.global [%0], [%1], 16;" \
                 :: "r"(dst), "l"(src) : "memory")
#define CP_COMMIT() asm volatile("cp.async.commit_group;" ::: "memory")
#define CP_WAIT(n)  asm volatile("cp.async.wait_group %0;" :: "n"(n) : "memory")

__device__ __forceinline__ void ldsm_x4(uint32_t addr, uint32_t* r) {
    asm volatile("ldmatrix.sync.aligned.m8n8.x4.shared.b16 {%0,%1,%2,%3}, [%4];"
                 : "=r"(r[0]), "=r"(r[1]), "=r"(r[2]), "=r"(r[3]) : "r"(addr));
}
__device__ __forceinline__ void mma_f16(float* c, const uint32_t* a,
                                        uint32_t b0, uint32_t b1) {
    asm volatile(
        "mma.sync.aligned.m16n8k16.row.col.f32.f16.f16.f32 "
        "{%0,%1,%2,%3}, {%4,%5,%6,%7}, {%8,%9}, {%0,%1,%2,%3};"
        : "+f"(c[0]), "+f"(c[1]), "+f"(c[2]), "+f"(c[3])
        : "r"(a[0]), "r"(a[1]), "r"(a[2]), "r"(a[3]), "r"(b0), "r"(b1));
}

// ============================================================
// prep: A'[i=d*128+c][j] -> fp16, transposed to [j][i]; batch counts
// ============================================================
__global__ void prep_kernel(const float* __restrict__ Ww,
                            const float* __restrict__ bw,
                            const float* __restrict__ Wl,
                            const int* __restrict__ didx) {
    int idx = blockIdx.x * blockDim.x + threadIdx.x;
    if (blockIdx.x == 0 && threadIdx.x < Bq) {
        int c = 0;
#pragma unroll
        for (int b = 0; b < Bq; b++) c += (didx[b] == (int)threadIdx.x);
        g_cnt[threadIdx.x] = c;
    }
    if (idx >= 4 * Cq * Cq) return;
    int d = idx >> 14;
    int c = (idx >> 7) & (Cq - 1);
    int j = idx & (Cq - 1);
    float acc = 0.f;
#pragma unroll
    for (int w = 0; w < Wq; w++) {
        float coef = (d < 3) ? Ww[d * Wq + w] : bw[w];
        acc = fmaf(coef, Wl[(c * Wq + w) * Cq + j], acc);
    }
    int i = (d << 7) | c;
    g_Ahf[(size_t)j * 512 + i] = __float2half_rn(acc);
}

// ============================================================
// convert: points fp32 -> fp16
// ============================================================
__global__ __launch_bounds__(256) void convert_kernel(const float* __restrict__ points) {
    size_t idx = ((size_t)blockIdx.x * 256 + threadIdx.x) * 4;
    float4 v = *reinterpret_cast<const float4*>(points + idx);
    *reinterpret_cast<__half2*>(g_Ph + idx) = __floats2half2_rn(v.x, v.y);
    *reinterpret_cast<__half2*>(g_Ph + idx + 2) = __floats2half2_rn(v.z, v.w);
}

// ============================================================
// gather: S[p,i] = sum_k coef[k,d] * points_h[s, nbr[k], c]; emit fp16
//   thread handles 4 channels (c4) x 4 points via LDG.64
// ============================================================
__global__ __launch_bounds__(128, 8) void gather_kernel(
    const float* __restrict__ lc,
    const int* __restrict__ nbr) {
    __shared__ ulonglong2 s_L[TPT][Kq];
    __shared__ uint32_t s_off[TPT][Kq];

    const int tid = threadIdx.x;
    const int s = blockIdx.y;
    if (g_cnt[s] == 0) return;
    const int p0 = blockIdx.x * TPT;
    const size_t base = ((size_t)s * Pq + p0) * Kq;

    for (int i = tid; i < TPT * Kq; i += 128) {
        int t = i >> 5, k = i & 31;
        s_off[t][k] = (uint32_t)nbr[base + (size_t)t * Kq + k] << 8;   // *256B row
        const float* Lp = lc + (base + (size_t)t * Kq + k) * 3;
        s_L[t][k] = make_ulonglong2(pk2(Lp[0], Lp[1]), pk2(Lp[2], 1.0f));
    }
    __syncthreads();

    const int c4 = tid & 31;          // channel quad: channels 4*c4 .. 4*c4+3
    const int h = tid >> 5;           // 0..3 point group
    const char* ptsb = (const char*)(g_Ph + (size_t)s * Nq * Cq) + 8 * c4;

#pragma unroll 1
    for (int tt = 0; tt < 4; tt++) {
        const int t = tt * 4 + h;
        unsigned long long a01[4], a23[4];
#pragma unroll
        for (int c = 0; c < 4; c++) { a01[c] = 0ull; a23[c] = 0ull; }
#pragma unroll
        for (int k = 0; k < Kq; k++) {
            uint2 w = *reinterpret_cast<const uint2*>(ptsb + s_off[t][k]);
            float2 v0 = __half22float2(h2_from_u32(w.x));
            float2 v1 = __half22float2(h2_from_u32(w.y));
            ulonglong2 L = s_L[t][k];
            unsigned long long p0v = pk2(v0.x, v0.x), p1v = pk2(v0.y, v0.y);
            unsigned long long p2v = pk2(v1.x, v1.x), p3v = pk2(v1.y, v1.y);
            fma2(a01[0], p0v, L.x); fma2(a23[0], p0v, L.y);
            fma2(a01[1], p1v, L.x); fma2(a23[1], p1v, L.y);
            fma2(a01[2], p2v, L.x); fma2(a23[2], p2v, L.y);
            fma2(a01[3], p3v, L.x); fma2(a23[3], p3v, L.y);
        }
        const size_t rb = ((size_t)s * Pq + p0 + t) * 512;
        float2 f01[4], f23[4];
#pragma unroll
        for (int c = 0; c < 4; c++) { f01[c] = up2(a01[c]); f23[c] = up2(a23[c]); }
        uint2 st;
        __half2 ha, hb;
        ha = __floats2half2_rn(f01[0].x, f01[1].x);
        hb = __floats2half2_rn(f01[2].x, f01[3].x);
        st.x = *reinterpret_cast<uint32_t*>(&ha);
        st.y = *reinterpret_cast<uint32_t*>(&hb);
        *reinterpret_cast<uint2*>(g_S + rb + 0 * 128 + 4 * c4) = st;
        ha = __floats2half2_rn(f01[0].y, f01[1].y);
        hb = __floats2half2_rn(f01[2].y, f01[3].y);
        st.x = *reinterpret_cast<uint32_t*>(&ha);
        st.y = *reinterpret_cast<uint32_t*>(&hb);
        *reinterpret_cast<uint2*>(g_S + rb + 1 * 128 + 4 * c4) = st;
        ha = __floats2half2_rn(f23[0].x, f23[1].x);
        hb = __floats2half2_rn(f23[2].x, f23[3].x);
        st.x = *reinterpret_cast<uint32_t*>(&ha);
        st.y = *reinterpret_cast<uint32_t*>(&hb);
        *reinterpret_cast<uint2*>(g_S + rb + 2 * 128 + 4 * c4) = st;
        ha = __floats2half2_rn(f23[0].y, f23[1].y);
        hb = __floats2half2_rn(f23[2].y, f23[3].y);
        st.x = *reinterpret_cast<uint32_t*>(&ha);
        st.y = *reinterpret_cast<uint32_t*>(&hb);
        *reinterpret_cast<uint2*>(g_S + rb + 3 * 128 + 4 * c4) = st;
    }
}

// ============================================================
// GEMM: Y[p,j] = S[p,i] * A'[j,i]^T  via mma.sync fp16
//   block tile 128p x 64j; K chunks of 64 (8 chunks); 2-stage;
//   ONE barrier per chunk (ISSUE placed after the sync -> race-free)
//   smem rows: 64 fp16 = 128B data, stride 144B (conflict-free ldmatrix)
// ============================================================
#define STILE_B 18432                // 128 rows * 144B
#define ATILE_B 9216                 // 64 rows * 144B
#define OFF_S   0
#define OFF_A   (STILE_B)
#define BUF_B   (STILE_B + ATILE_B)       // 27648
#define GSM_TOTAL (2 * BUF_B)             // 55296 (epilogue 64*132*4=33792 fits)

__global__ __launch_bounds__(256, 3) void gemm_kernel(const float* __restrict__ bl) {
    extern __shared__ __align__(128) char sm[];
    const int tid = threadIdx.x;
    const int wid = tid >> 5;
    const int L = tid & 31;
    const int srcb = blockIdx.y;
    if (g_cnt[srcb] == 0) return;
    const int pt = blockIdx.x >> 1;
    const int jh = blockIdx.x & 1;     // which 64-j half
    const int wm = wid >> 1;           // 0..3  (p dim, 32 each)
    const int wn = wid & 1;            // 0..1  (j dim, 32 each)

    const uint32_t smb = smem_to_u32(sm);
    const __half* Sp = g_S + ((size_t)srcb * Pq + pt * 128) * 512;
    const __half* Ah = g_Ahf + (size_t)(jh * 64) * 512;

    float acc[2][4][4];
#pragma unroll
    for (int mt = 0; mt < 2; mt++)
#pragma unroll
        for (int nt = 0; nt < 4; nt++)
#pragma unroll
            for (int q = 0; q < 4; q++) acc[mt][nt][q] = 0.f;

    const int grp = L >> 3, lr = L & 7;
    const uint32_t aRow = (uint32_t)(wm * 32 + (grp & 1) * 8 + lr) * 144
                        + (uint32_t)(grp >> 1) * 16;
    const uint32_t bRow = (uint32_t)(wn * 32 + (grp >> 1) * 8 + lr) * 144
                        + (uint32_t)(grp & 1) * 16;

#define ISSUE(kc, buf) do {                                                     \
        uint32_t bb = smb + (uint32_t)(buf) * BUF_B;                            \
        _Pragma("unroll")                                                       \
        for (int ii = 0; ii < 4; ii++) {                                        \
            int u = tid + ii * 256;                                             \
            int row = u >> 3, seg = u & 7;                                      \
            CP_ASYNC16(bb + OFF_S + (uint32_t)row * 144 + (uint32_t)seg * 16,   \
                       (const char*)(Sp + (size_t)row * 512 + (kc) * 64 + seg * 8)); \
        }                                                                       \
        _Pragma("unroll")                                                       \
        for (int ii = 0; ii < 2; ii++) {                                        \
            int u = tid + ii * 256;                                             \
            int row = u >> 3, seg = u & 7;                                      \
            CP_ASYNC16(bb + OFF_A + (uint32_t)row * 144 + (uint32_t)seg * 16,   \
                       (const char*)(Ah + (size_t)row * 512 + (kc) * 64 + seg * 8)); \
        }                                                                       \
        CP_COMMIT();                                                            \
    } while (0)

    ISSUE(0, 0);

#pragma unroll 1
    for (int kc = 0; kc < 8; kc++) {
        CP_WAIT(0);
        __syncthreads();
        if (kc < 7) ISSUE(kc + 1, (kc + 1) & 1);   // safe: all readers of that
                                                   // buffer passed the sync
        const uint32_t bb = smb + (uint32_t)(kc & 1) * BUF_B;
#pragma unroll
        for (int ks = 0; ks < 4; ks++) {
            uint32_t af[2][4];
#pragma unroll
            for (int mt = 0; mt < 2; mt++) {
                uint32_t ao = aRow + (uint32_t)mt * (16 * 144) + (uint32_t)ks * 32;
                ldsm_x4(bb + OFF_S + ao, af[mt]);
            }
#pragma unroll
            for (int ng = 0; ng < 2; ng++) {
                uint32_t bh[4];
                uint32_t bo = bRow + (uint32_t)ng * (16 * 144) + (uint32_t)ks * 32;
                ldsm_x4(bb + OFF_A + bo, bh);
#pragma unroll
                for (int mt = 0; mt < 2; mt++) {
#pragma unroll
                    for (int t2 = 0; t2 < 2; t2++) {
                        mma_f16(acc[mt][2 * ng + t2], af[mt],
                                bh[2 * t2], bh[2 * t2 + 1]);
                    }
                }
            }
        }
    }
    __syncthreads();

    // ---- epilogue: C frags -> smem [64j][132] -> coalesced fp16 Y + LN partials ----
    float* yt = (float*)sm;
    {
        const int pb = wm * 32 + (L >> 2);
        const int jb = wn * 32 + ((L & 3) << 1);
#pragma unroll
        for (int mt = 0; mt < 2; mt++) {
#pragma unroll
            for (int nt = 0; nt < 4; nt++) {
                const float* c = acc[mt][nt];
                int p = pb + mt * 16;
                int j = jb + nt * 8;
                yt[j * 132 + p] = c[0];
                yt[(j + 1) * 132 + p] = c[1];
                yt[j * 132 + p + 8] = c[2];
                yt[(j + 1) * 132 + p + 8] = c[3];
            }
        }
    }
    __syncthreads();

    const int blk2 = srcb * NPTILE + pt;
#pragma unroll 1
    for (int rr = 0; rr < 8; rr++) {
        int j = wid * 8 + rr;          // local j in [0,64)
        int jg = jh * 64 + j;          // global output channel
        float blj = __ldg(bl + jg);
        float4 v = *reinterpret_cast<const float4*>(yt + j * 132 + L * 4);
        v.x += blj; v.y += blj; v.z += blj; v.w += blj;
        __half2 h0 = __floats2half2_rn(v.x, v.y);
        __half2 h1 = __floats2half2_rn(v.z, v.w);
        uint2 st;
        st.x = *reinterpret_cast<uint32_t*>(&h0);
        st.y = *reinterpret_cast<uint32_t*>(&h1);
        *reinterpret_cast<uint2*>(
            g_Yth + ((size_t)srcb * Cq + jg) * Pq + pt * 128 + L * 4) = st;
        float ls = (v.x + v.y) + (v.z + v.w);
        float lq = (v.x * v.x + v.y * v.y) + (v.z * v.z + v.w * v.w);
#pragma unroll
        for (int o = 16; o > 0; o >>= 1) {
            ls += __shfl_xor_sync(0xFFFFFFFFu, ls, o);
            lq += __shfl_xor_sync(0xFFFFFFFFu, lq, o);
        }
        if (L == 0) {
            g_ps[(size_t)blk2 * Cq + jg] = ls;
            g_pq[(size_t)blk2 * Cq + jg] = lq;
        }
    }
}

// ============================================================
// stats: single-block deterministic multiplicity-weighted reduction
//   FIXED: each thread-group g covers rows (0..31)*8+g  (all 256 rows)
// ============================================================
__global__ __launch_bounds__(1024) void stats_kernel(const float* __restrict__ gamma,
                                                     const float* __restrict__ beta) {
    __shared__ float ss[8][Cq], sq[8][Cq];
    const int j = threadIdx.x & 127;
    const int g = threadIdx.x >> 7;   // 0..7
    float s0 = 0.f, s1 = 0.f, s2 = 0.f, s3 = 0.f;
    float q0 = 0.f, q1 = 0.f, q2 = 0.f, q3 = 0.f;
#pragma unroll
    for (int rr = 0; rr < NBLK2 / 8; rr += 4) {    // 8 iters of 4, rows (rr+i)*8+g
        int r0 = (rr + 0) * 8 + g;
        int r1 = (rr + 1) * 8 + g;
        int r2 = (rr + 2) * 8 + g;
        int r3 = (rr + 3) * 8 + g;
        float w0 = (float)g_cnt[r0 >> 5];
        float w1 = (float)g_cnt[r1 >> 5];
        float w2 = (float)g_cnt[r2 >> 5];
        float w3 = (float)g_cnt[r3 >> 5];
        s0 += w0 * g_ps[(size_t)r0 * Cq + j];
        s1 += w1 * g_ps[(size_t)r1 * Cq + j];
        s2 += w2 * g_ps[(size_t)r2 * Cq + j];
        s3 += w3 * g_ps[(size_t)r3 * Cq + j];
        q0 += w0 * g_pq[(size_t)r0 * Cq + j];
        q1 += w1 * g_pq[(size_t)r1 * Cq + j];
        q2 += w2 * g_pq[(size_t)r2 * Cq + j];
        q3 += w3 * g_pq[(size_t)r3 * Cq + j];
    }
    ss[g][j] = (s0 + s1) + (s2 + s3);
    sq[g][j] = (q0 + q1) + (q2 + q3);
    __syncthreads();
    if (g == 0) {
        float S = 0.f, Q = 0.f;
#pragma unroll
        for (int i = 0; i < 8; i++) { S += ss[i][j]; Q += sq[i][j]; }
        const float inv = 1.0f / (float)(Bq * Pq);
        float mean = S * inv;
        float var = Q * inv - mean * mean;
        float sc = rsqrtf(var + EPSq) * gamma[j];
        g_scale[j] = sc;
        g_shift[j] = beta[j] - mean * sc;
    }
}

// ============================================================
// out: scale+shift+relu, coalesced fp16 read -> fp32 write
// ============================================================
__global__ __launch_bounds__(256) void out_kernel(float* __restrict__ out,
                                                  const int* __restrict__ didx) {
    const int b = blockIdx.x >> 7;
    const int j = blockIdx.x & 127;
    const int src = didx[b];
    const float sc = g_scale[j];
    const float sh = g_shift[j];
    const uint4* in = reinterpret_cast<const uint4*>(
        g_Yth + ((size_t)src * Cq + j) * Pq);
    float4* op = reinterpret_cast<float4*>(out + (size_t)blockIdx.x * Pq);
#pragma unroll
    for (int k = 0; k < 2; k++) {
        int idx = threadIdx.x + k * 256;      // 512 uint4 per row
        uint4 v = in[idx];
        float2 a0 = __half22float2(h2_from_u32(v.x));
        float2 a1 = __half22float2(h2_from_u32(v.y));
        float2 a2 = __half22float2(h2_from_u32(v.z));
        float2 a3 = __half22float2(h2_from_u32(v.w));
        float4 o0, o1;
        o0.x = fmaxf(fmaf(a0.x, sc, sh), 0.f);
        o0.y = fmaxf(fmaf(a0.y, sc, sh), 0.f);
        o0.z = fmaxf(fmaf(a1.x, sc, sh), 0.f);
        o0.w = fmaxf(fmaf(a1.y, sc, sh), 0.f);
        o1.x = fmaxf(fmaf(a2.x, sc, sh), 0.f);
        o1.y = fmaxf(fmaf(a2.y, sc, sh), 0.f);
        o1.z = fmaxf(fmaf(a3.x, sc, sh), 0.f);
        o1.w = fmaxf(fmaf(a3.y, sc, sh), 0.f);
        op[idx * 2] = o0;
        op[idx * 2 + 1] = o1;
    }
}

// ============================================================
// Launch
// ============================================================
extern "C" void kernel_launch(void* const* d_in, const int* in_sizes, int n_in,
                              void* d_out, int out_size) {
    const float* xyz    = (const float*)d_in[0];
    const float* points = (const float*)d_in[1];
    const float* lc     = (const float*)d_in[2];
    const int*   nbr    = (const int*)d_in[3];
    const int*   didx   = (const int*)d_in[4];
    const float* Ww     = (const float*)d_in[5];
    const float* bw     = (const float*)d_in[6];
    const float* Wl     = (const float*)d_in[7];
    const float* bl     = (const float*)d_in[8];
    const float* gamma  = (const float*)d_in[9];
    const float* beta   = (const float*)d_in[10];
    float* out = (float*)d_out;

    cudaMemcpyAsync(out, xyz, (size_t)Bq * Pq * 3 * sizeof(float),
                    cudaMemcpyDeviceToDevice, 0);

    cudaFuncSetAttribute(gemm_kernel,
                         cudaFuncAttributeMaxDynamicSharedMemorySize, GSM_TOTAL);

    prep_kernel<<<256, 256>>>(Ww, bw, Wl, didx);
    convert_kernel<<<(Bq * Nq * Cq) / 1024, 256>>>(points);

    dim3 gg(GBLK_PER_B, Bq);
    gather_kernel<<<gg, 128>>>(lc, nbr);

    dim3 g2(NPTILE * 2, Bq);
    gemm_kernel<<<g2, 256, GSM_TOTAL>>>(bl);

    stats_kernel<<<1, 1024>>>(gamma, beta);

    out_kernel<<<Bq * Cq, 256>>>(out + (size_t)Bq * Pq * 3, didx);
}